// round 2
// baseline (speedup 1.0000x reference)
#include <cuda_runtime.h>
#include <math.h>

#define NN 100000
#define NE 1600000
#define ET 1700000          // NE + NN self loops
#define NB 98               // ceil(NN/1024)

// ---------------- static scratch (no allocations allowed) ----------------
__device__ __align__(256) float g_hl[NN * 128];
__device__ __align__(256) float g_hr[NN * 128];
__device__ __align__(256) float g_h [NN * 128];
__device__ int g_deg[NN];
__device__ int g_tmp[NN];
__device__ int g_rowptr[NN + 1];
__device__ int g_fill[NN];
__device__ int g_esrc[ET];
__device__ int g_src[ET];
__device__ int g_dst[ET];
__device__ int g_bsums[128];
__device__ int g_is64;

// ---------------- edge-index ingestion (dtype-agnostic) ----------------
// If edge_index is int64 (little-endian, values < 2^31), every odd int32 word
// is 0. With random int32 indices in [0,100000), 1024 consecutive zeros is
// impossible in practice.
__global__ void detect_k(const int* __restrict__ ei32) {
    if (threadIdx.x == 0 && blockIdx.x == 0) {
        int acc = 0;
        for (int i = 0; i < 1024; i++) acc |= ei32[2 * i + 1];
        g_is64 = (acc == 0) ? 1 : 0;
    }
}

__global__ void convert_k(const void* __restrict__ ei) {
    int i = blockIdx.x * blockDim.x + threadIdx.x;
    if (i >= ET) return;
    int s, d;
    if (i < NE) {
        if (g_is64) {
            s = (int)((const long long*)ei)[i];
            d = (int)((const long long*)ei)[NE + i];
        } else {
            s = ((const int*)ei)[i];
            d = ((const int*)ei)[NE + i];
        }
    } else {
        s = d = i - NE;                       // appended self loops
    }
    s = min(max(s, 0), NN - 1);               // defensive: never fault
    d = min(max(d, 0), NN - 1);
    g_src[i] = s;
    g_dst[i] = d;
}

// ---------------- CSR build ----------------
__global__ void count_deg_k() {
    int i = blockIdx.x * blockDim.x + threadIdx.x;
    if (i >= ET) return;
    atomicAdd(&g_deg[g_dst[i]], 1);
}

__global__ void scan1_k() {
    __shared__ int sh[1024];
    int i = blockIdx.x * 1024 + threadIdx.x;
    int v = (i < NN) ? g_deg[i] : 0;
    sh[threadIdx.x] = v;
    __syncthreads();
    for (int off = 1; off < 1024; off <<= 1) {
        int t = (threadIdx.x >= off) ? sh[threadIdx.x - off] : 0;
        __syncthreads();
        sh[threadIdx.x] += t;
        __syncthreads();
    }
    if (i < NN) g_tmp[i] = sh[threadIdx.x];
    if (threadIdx.x == 1023) g_bsums[blockIdx.x] = sh[1023];
}

__global__ void scan2_k() {
    if (threadIdx.x == 0 && blockIdx.x == 0) {
        int acc = 0;
        for (int b = 0; b < NB; b++) { int v = g_bsums[b]; g_bsums[b] = acc; acc += v; }
    }
}

__global__ void scan3_k() {
    int i = blockIdx.x * blockDim.x + threadIdx.x;
    if (i < NN) g_rowptr[i + 1] = g_tmp[i] + g_bsums[i >> 10];
    if (i == 0) g_rowptr[0] = 0;
}

__global__ void scatter_k() {
    int i = blockIdx.x * blockDim.x + threadIdx.x;
    if (i >= ET) return;
    int pos = atomicAdd(&g_fill[g_dst[i]], 1);
    g_esrc[pos] = g_src[i];
}

// ---------------- GEMM: C[n,oc] = A[n,128] @ W[128,oc] ----------------
// BM=128, BN=64, 256 threads, per-thread 8x4 microtile.
__global__ __launch_bounds__(256) void gemm_k(
    const float* __restrict__ A, const float* __restrict__ W,
    float* __restrict__ C, int n, int oc)
{
    __shared__ __align__(16) float As[16][128];
    __shared__ __align__(16) float Ws[16][64];
    const int tid = threadIdx.x;
    const int tx = tid & 15, ty = tid >> 4;
    const int row0 = blockIdx.x * 128;
    const int col0 = blockIdx.y * 64;

    float acc[8][4];
#pragma unroll
    for (int i = 0; i < 8; i++)
#pragma unroll
        for (int j = 0; j < 4; j++) acc[i][j] = 0.f;

    for (int kk = 0; kk < 128; kk += 16) {
#pragma unroll
        for (int t = tid; t < 2048; t += 256) {
            int m = t >> 4, k = t & 15;
            int r = row0 + m;
            As[k][m] = (r < n) ? A[r * 128 + kk + k] : 0.f;
        }
#pragma unroll
        for (int t = tid; t < 1024; t += 256) {
            int k = t >> 6, c = t & 63;
            Ws[k][c] = W[(kk + k) * oc + col0 + c];
        }
        __syncthreads();
#pragma unroll
        for (int k = 0; k < 16; k++) {
            float4 a0 = *reinterpret_cast<const float4*>(&As[k][ty * 8]);
            float4 a1 = *reinterpret_cast<const float4*>(&As[k][ty * 8 + 4]);
            float4 bb = *reinterpret_cast<const float4*>(&Ws[k][tx * 4]);
            float a[8] = {a0.x, a0.y, a0.z, a0.w, a1.x, a1.y, a1.z, a1.w};
            float b[4] = {bb.x, bb.y, bb.z, bb.w};
#pragma unroll
            for (int i = 0; i < 8; i++)
#pragma unroll
                for (int j = 0; j < 4; j++) acc[i][j] = fmaf(a[i], b[j], acc[i][j]);
        }
        __syncthreads();
    }
#pragma unroll
    for (int i = 0; i < 8; i++) {
        int r = row0 + ty * 8 + i;
        if (r < n) {
            float4 o = {acc[i][0], acc[i][1], acc[i][2], acc[i][3]};
            *reinterpret_cast<float4*>(&C[r * oc + col0 + tx * 4]) = o;
        }
    }
}

// ---------------- fused edge kernel: online segment softmax + aggregate ----
// One warp per destination node. H heads, CH total channels, V = CH/32 per lane.
template <int H, int CH>
__global__ __launch_bounds__(256) void gat_edge(
    const float* __restrict__ hl, const float* __restrict__ hr,
    const float* __restrict__ att, const float* __restrict__ bias,
    float* __restrict__ out)
{
    constexpr int V = CH / 32;
    const int w = (blockIdx.x * blockDim.x + threadIdx.x) >> 5;
    const int lane = threadIdx.x & 31;
    if (w >= NN) return;

    float attv[V], hrv[V], acc[V];
#pragma unroll
    for (int v = 0; v < V; v++) attv[v] = att[lane * V + v];

    if (V == 4) {
        float4 t = __ldg(reinterpret_cast<const float4*>(hl - hl + hr) + w * 32 + lane);
        hrv[0] = t.x; hrv[1] = t.y; hrv[2] = t.z; hrv[3] = t.w;
    } else {
        float2 t = __ldg(reinterpret_cast<const float2*>(hr) + w * 32 + lane);
        hrv[0] = t.x; hrv[1] = t.y;
    }
#pragma unroll
    for (int v = 0; v < V; v++) acc[v] = 0.f;

    float m = -INFINITY, lsum = 0.f;
    const int e0 = g_rowptr[w], e1 = g_rowptr[w + 1];

    for (int e = e0; e < e1; e++) {
        int s = __ldg(&g_esrc[e]);
        float hv[V];
        if (V == 4) {
            float4 t = __ldg(reinterpret_cast<const float4*>(hl) + s * 32 + lane);
            hv[0] = t.x; hv[1] = t.y; hv[2] = t.z; hv[3] = t.w;
        } else {
            float2 t = __ldg(reinterpret_cast<const float2*>(hl) + s * 32 + lane);
            hv[0] = t.x; hv[1] = t.y;
        }
        float p = 0.f;
#pragma unroll
        for (int v = 0; v < V; v++) {
            float t = hv[v] + hrv[v];
            t = (t > 0.f) ? t : 0.2f * t;          // LeakyReLU(0.2)
            p = fmaf(t, attv[v], p);
        }
        // reduce over the 32/H lanes of this head (groups are lane-contiguous)
#pragma unroll
        for (int off = (32 / H) >> 1; off > 0; off >>= 1)
            p += __shfl_xor_sync(0xffffffffu, p, off);

        float mn = fmaxf(m, p);
        float sc = __expf(m - mn);                 // 0 on first edge (m = -inf)
        float ww = __expf(p - mn);
        lsum = lsum * sc + ww;
#pragma unroll
        for (int v = 0; v < V; v++) acc[v] = fmaf(acc[v], sc, ww * hv[v]);
        m = mn;
    }

    float inv = 1.f / (lsum + 1e-16f);
    if (V == 4) {
        float4 o;
        o.x = fmaxf(fmaf(acc[0], inv, bias[lane * 4 + 0]), 0.f);
        o.y = fmaxf(fmaf(acc[1], inv, bias[lane * 4 + 1]), 0.f);
        o.z = fmaxf(fmaf(acc[2], inv, bias[lane * 4 + 2]), 0.f);
        o.w = fmaxf(fmaf(acc[3], inv, bias[lane * 4 + 3]), 0.f);
        reinterpret_cast<float4*>(out)[w * 32 + lane] = o;
    } else {
        float2 o;
        o.x = fmaxf(fmaf(acc[0], inv, bias[lane * 2 + 0]), 0.f);
        o.y = fmaxf(fmaf(acc[1], inv, bias[lane * 2 + 1]), 0.f);
        reinterpret_cast<float2*>(out)[w * 32 + lane] = o;
    }
}

// ---------------- launch ----------------
extern "C" void kernel_launch(void* const* d_in, const int* in_sizes, int n_in,
                              void* d_out, int out_size)
{
    const float* x   = (const float*)d_in[0];
    const void*  ei  = d_in[1];
    const float *W0l = (const float*)d_in[2],  *W0r = (const float*)d_in[3];
    const float *a0  = (const float*)d_in[4],  *b0  = (const float*)d_in[5];
    const float *W1l = (const float*)d_in[6],  *W1r = (const float*)d_in[7];
    const float *a1  = (const float*)d_in[8],  *b1  = (const float*)d_in[9];
    const float *W2l = (const float*)d_in[10], *W2r = (const float*)d_in[11];
    const float *a2  = (const float*)d_in[12], *b2  = (const float*)d_in[13];
    float* out = (float*)d_out;

    void *p_deg, *p_rowptr, *p_fill, *p_hl, *p_hr, *p_h;
    cudaGetSymbolAddress(&p_deg, g_deg);
    cudaGetSymbolAddress(&p_rowptr, g_rowptr);
    cudaGetSymbolAddress(&p_fill, g_fill);
    cudaGetSymbolAddress(&p_hl, g_hl);
    cudaGetSymbolAddress(&p_hr, g_hr);
    cudaGetSymbolAddress(&p_h, g_h);
    float* hl = (float*)p_hl;
    float* hr = (float*)p_hr;
    float* h  = (float*)p_h;

    const int eb = (ET + 255) / 256;

    // ingest edge indices (int32 or int64), then CSR by destination
    detect_k<<<1, 32>>>((const int*)ei);
    convert_k<<<eb, 256>>>(ei);
    cudaMemsetAsync(p_deg, 0, NN * sizeof(int));
    count_deg_k<<<eb, 256>>>();
    scan1_k<<<NB, 1024>>>();
    scan2_k<<<1, 32>>>();
    scan3_k<<<(NN + 255) / 256, 256>>>();
    cudaMemcpyAsync(p_fill, p_rowptr, NN * sizeof(int), cudaMemcpyDeviceToDevice);
    scatter_k<<<eb, 256>>>();

    const dim3 gg((NN + 127) / 128, 2);
    const dim3 gg2((NN + 127) / 128, 1);
    const int egrid = (NN * 32 + 255) / 256;

    // layer 0
    gemm_k<<<gg, 256>>>(x, W0l, hl, NN, 128);
    gemm_k<<<gg, 256>>>(x, W0r, hr, NN, 128);
    gat_edge<4, 128><<<egrid, 256>>>(hl, hr, a0, b0, h);
    // layer 1
    gemm_k<<<gg, 256>>>(h, W1l, hl, NN, 128);
    gemm_k<<<gg, 256>>>(h, W1r, hr, NN, 128);
    gat_edge<4, 128><<<egrid, 256>>>(hl, hr, a1, b1, h);
    // layer 2
    gemm_k<<<gg2, 256>>>(h, W2l, hl, NN, 64);
    gemm_k<<<gg2, 256>>>(h, W2r, hr, NN, 64);
    gat_edge<1, 64><<<egrid, 256>>>(hl, hr, a2, b2, out);
}

// round 3
// speedup vs baseline: 1.2246x; 1.2246x over previous
#include <cuda_runtime.h>
#include <math.h>

#define NN 100000
#define NE 1600000
#define ET 1700000          // NE + NN self loops
#define NB 98               // ceil(NN/1024)

// GEMM tiling
#define BM 128
#define BN 64
#define BK 16
#define AP 20               // A smem pitch ([m][k], conflict-free: 20*gid mod 32 distinct)
#define BP 72               // B smem pitch ([k][n], conflict-free: 8k+n distinct)

// ---------------- static scratch (no allocations allowed) ----------------
__device__ __align__(256) float g_hl[NN * 128];
__device__ __align__(256) float g_hr[NN * 128];
__device__ __align__(256) float g_h [NN * 128];
__device__ int g_deg[NN];
__device__ int g_tmp[NN];
__device__ int g_rowptr[NN + 1];
__device__ int g_fill[NN];
__device__ int g_esrc[ET];
__device__ int g_src[ET];
__device__ int g_dst[ET];
__device__ int g_bsums[128];
__device__ int g_is64;

// ---------------- ingestion + CSR ----------------
// zero g_deg across the grid; block 0 thread 0 also detects index dtype.
__global__ void zero_detect_k(const int* __restrict__ ei32) {
    int i = blockIdx.x * blockDim.x + threadIdx.x;
    if (i < NN) g_deg[i] = 0;
    if (i == 0) {
        int acc = 0;
        for (int j = 0; j < 1024; j++) acc |= ei32[2 * j + 1];
        g_is64 = (acc == 0) ? 1 : 0;   // int64 little-endian => high words all 0
    }
}

__global__ void convert_count_k(const void* __restrict__ ei) {
    int i = blockIdx.x * blockDim.x + threadIdx.x;
    if (i >= ET) return;
    int s, d;
    if (i < NE) {
        if (g_is64) {
            s = (int)((const long long*)ei)[i];
            d = (int)((const long long*)ei)[NE + i];
        } else {
            s = ((const int*)ei)[i];
            d = ((const int*)ei)[NE + i];
        }
    } else {
        s = d = i - NE;                       // appended self loops
    }
    s = min(max(s, 0), NN - 1);               // defensive: never fault
    d = min(max(d, 0), NN - 1);
    g_src[i] = s;
    g_dst[i] = d;
    atomicAdd(&g_deg[d], 1);
}

__global__ void scan1_k() {
    __shared__ int sh[1024];
    int i = blockIdx.x * 1024 + threadIdx.x;
    int v = (i < NN) ? g_deg[i] : 0;
    sh[threadIdx.x] = v;
    __syncthreads();
    for (int off = 1; off < 1024; off <<= 1) {
        int t = (threadIdx.x >= off) ? sh[threadIdx.x - off] : 0;
        __syncthreads();
        sh[threadIdx.x] += t;
        __syncthreads();
    }
    if (i < NN) g_tmp[i] = sh[threadIdx.x];
    if (threadIdx.x == 1023) g_bsums[blockIdx.x] = sh[1023];
}

__global__ void scan2_k() {
    if (threadIdx.x == 0 && blockIdx.x == 0) {
        int acc = 0;
        for (int b = 0; b < NB; b++) { int v = g_bsums[b]; g_bsums[b] = acc; acc += v; }
    }
}

__global__ void scan3_k() {
    int i = blockIdx.x * blockDim.x + threadIdx.x;
    if (i < NN) {
        int incl = g_tmp[i] + g_bsums[i >> 10];
        g_rowptr[i + 1] = incl;
        g_fill[i] = incl - g_deg[i];           // exclusive prefix = fill cursor
    }
    if (i == 0) g_rowptr[0] = 0;
}

__global__ void scatter_k() {
    int i = blockIdx.x * blockDim.x + threadIdx.x;
    if (i >= ET) return;
    int pos = atomicAdd(&g_fill[g_dst[i]], 1);
    g_esrc[pos] = g_src[i];
}

// ---------------- tf32x3 tensor-core GEMM ----------------
__device__ __forceinline__ unsigned f2tf(float x) {
    unsigned u;
    asm("cvt.rna.tf32.f32 %0, %1;" : "=r"(u) : "f"(x));
    return u;
}

__device__ __forceinline__ void mma8(float* c, const unsigned* a, const unsigned* b) {
    asm volatile(
        "mma.sync.aligned.m16n8k8.row.col.f32.tf32.tf32.f32 "
        "{%0,%1,%2,%3}, {%4,%5,%6,%7}, {%8,%9}, {%0,%1,%2,%3};"
        : "+f"(c[0]), "+f"(c[1]), "+f"(c[2]), "+f"(c[3])
        : "r"(a[0]), "r"(a[1]), "r"(a[2]), "r"(a[3]), "r"(b[0]), "r"(b[1]));
}

// C[n, oc] = A[n,128] @ W[128, oc].  tf32x3: hi*hi + hi*lo + lo*hi.
__global__ __launch_bounds__(256) void gemm_tf32_k(
    const float* __restrict__ A, const float* __restrict__ W,
    float* __restrict__ C, int n, int oc)
{
    __shared__ unsigned Ah[BM * AP], Al[BM * AP];
    __shared__ unsigned Bh[BK * BP], Bl[BK * BP];

    const int tid = threadIdx.x;
    const int lane = tid & 31, wid = tid >> 5;
    const int wm = wid >> 1, wn = wid & 1;       // 4 x 2 warp grid
    const int gid = lane >> 2, tig = lane & 3;
    const int row0 = blockIdx.x * BM;
    const int col0 = blockIdx.y * BN;

    float acc[2][4][4];
#pragma unroll
    for (int i = 0; i < 2; i++)
#pragma unroll
        for (int j = 0; j < 4; j++)
#pragma unroll
            for (int r = 0; r < 4; r++) acc[i][j][r] = 0.f;

    const int ar = tid >> 1, ah_half = (tid & 1) * 8;      // A: 128 rows x 16 k
    const int br = tid >> 4, bc = (tid & 15) * 4;          // B: 16 rows x 64 n

    for (int kk = 0; kk < 128; kk += BK) {
        // A tile -> smem (hi/lo split)
        {
            float v[8];
            if (row0 + ar < n) {
                float4 v0 = *reinterpret_cast<const float4*>(A + (row0 + ar) * 128 + kk + ah_half);
                float4 v1 = *reinterpret_cast<const float4*>(A + (row0 + ar) * 128 + kk + ah_half + 4);
                v[0] = v0.x; v[1] = v0.y; v[2] = v0.z; v[3] = v0.w;
                v[4] = v1.x; v[5] = v1.y; v[6] = v1.z; v[7] = v1.w;
            } else {
#pragma unroll
                for (int q = 0; q < 8; q++) v[q] = 0.f;
            }
#pragma unroll
            for (int q = 0; q < 8; q++) {
                unsigned hi = f2tf(v[q]);
                float lo = v[q] - __uint_as_float(hi);
                Ah[ar * AP + ah_half + q] = hi;
                Al[ar * AP + ah_half + q] = f2tf(lo);
            }
        }
        // B tile -> smem (hi/lo split)
        {
            float4 v = *reinterpret_cast<const float4*>(W + (kk + br) * oc + col0 + bc);
            float b4[4] = {v.x, v.y, v.z, v.w};
#pragma unroll
            for (int q = 0; q < 4; q++) {
                unsigned hi = f2tf(b4[q]);
                float lo = b4[q] - __uint_as_float(hi);
                Bh[br * BP + bc + q] = hi;
                Bl[br * BP + bc + q] = f2tf(lo);
            }
        }
        __syncthreads();

#pragma unroll
        for (int ks = 0; ks < 2; ks++) {
            const int k0 = ks * 8;
            unsigned ah[2][4], al[2][4], bh[4][2], bl[4][2];
#pragma unroll
            for (int i = 0; i < 2; i++) {
                int m0 = wm * 32 + i * 16;
                ah[i][0] = Ah[(m0 + gid) * AP + k0 + tig];
                ah[i][1] = Ah[(m0 + gid + 8) * AP + k0 + tig];
                ah[i][2] = Ah[(m0 + gid) * AP + k0 + tig + 4];
                ah[i][3] = Ah[(m0 + gid + 8) * AP + k0 + tig + 4];
                al[i][0] = Al[(m0 + gid) * AP + k0 + tig];
                al[i][1] = Al[(m0 + gid + 8) * AP + k0 + tig];
                al[i][2] = Al[(m0 + gid) * AP + k0 + tig + 4];
                al[i][3] = Al[(m0 + gid + 8) * AP + k0 + tig + 4];
            }
#pragma unroll
            for (int j = 0; j < 4; j++) {
                int c = wn * 32 + j * 8 + gid;
                bh[j][0] = Bh[(k0 + tig) * BP + c];
                bh[j][1] = Bh[(k0 + tig + 4) * BP + c];
                bl[j][0] = Bl[(k0 + tig) * BP + c];
                bl[j][1] = Bl[(k0 + tig + 4) * BP + c];
            }
#pragma unroll
            for (int i = 0; i < 2; i++)
#pragma unroll
                for (int j = 0; j < 4; j++) {
                    mma8(acc[i][j], ah[i], bh[j]);
                    mma8(acc[i][j], ah[i], bl[j]);
                    mma8(acc[i][j], al[i], bh[j]);
                }
        }
        __syncthreads();
    }

#pragma unroll
    for (int i = 0; i < 2; i++) {
        int rbase = row0 + wm * 32 + i * 16 + gid;
#pragma unroll
        for (int j = 0; j < 4; j++) {
            int c = col0 + wn * 32 + j * 8 + 2 * tig;
            if (rbase < n)
                *reinterpret_cast<float2*>(C + rbase * oc + c) = make_float2(acc[i][j][0], acc[i][j][1]);
            if (rbase + 8 < n)
                *reinterpret_cast<float2*>(C + (rbase + 8) * oc + c) = make_float2(acc[i][j][2], acc[i][j][3]);
        }
    }
}

// ---------------- fused edge kernel: online segment softmax + aggregate ----
// One warp per destination node. H heads, CH total channels, V = CH/32 per lane.
template <int H, int CH>
__global__ __launch_bounds__(256) void gat_edge(
    const float* __restrict__ hl, const float* __restrict__ hr,
    const float* __restrict__ att, const float* __restrict__ bias,
    float* __restrict__ out)
{
    constexpr int V = CH / 32;
    const int w = (blockIdx.x * blockDim.x + threadIdx.x) >> 5;
    const int lane = threadIdx.x & 31;
    if (w >= NN) return;

    float attv[V], hrv[V], acc[V];
#pragma unroll
    for (int v = 0; v < V; v++) attv[v] = att[lane * V + v];

    if (V == 4) {
        float4 t = __ldg(reinterpret_cast<const float4*>(hr) + w * 32 + lane);
        hrv[0] = t.x; hrv[1] = t.y; hrv[2] = t.z; hrv[3] = t.w;
    } else {
        float2 t = __ldg(reinterpret_cast<const float2*>(hr) + w * 32 + lane);
        hrv[0] = t.x; hrv[1] = t.y;
    }
#pragma unroll
    for (int v = 0; v < V; v++) acc[v] = 0.f;

    float m = -INFINITY, lsum = 0.f;
    const int e0 = g_rowptr[w], e1 = g_rowptr[w + 1];

    // helper: per-edge online-softmax update given gathered features
    auto update = [&](const float* hv) {
        float p = 0.f;
#pragma unroll
        for (int v = 0; v < V; v++) {
            float t = hv[v] + hrv[v];
            t = (t > 0.f) ? t : 0.2f * t;          // LeakyReLU(0.2)
            p = fmaf(t, attv[v], p);
        }
#pragma unroll
        for (int off = (32 / H) >> 1; off > 0; off >>= 1)
            p += __shfl_xor_sync(0xffffffffu, p, off);
        float mn = fmaxf(m, p);
        float sc = __expf(m - mn);                 // 0 on first edge (m = -inf)
        float ww = __expf(p - mn);
        lsum = lsum * sc + ww;
#pragma unroll
        for (int v = 0; v < V; v++) acc[v] = fmaf(acc[v], sc, ww * hv[v]);
        m = mn;
    };

    int e = e0;
    // 4-wide software pipeline: issue 4 index loads + 4 gathers before updates
    for (; e + 4 <= e1; e += 4) {
        int s0 = __ldg(&g_esrc[e]);
        int s1 = __ldg(&g_esrc[e + 1]);
        int s2 = __ldg(&g_esrc[e + 2]);
        int s3 = __ldg(&g_esrc[e + 3]);
        float hv0[V], hv1[V], hv2[V], hv3[V];
        if (V == 4) {
            float4 t0 = __ldg(reinterpret_cast<const float4*>(hl) + s0 * 32 + lane);
            float4 t1 = __ldg(reinterpret_cast<const float4*>(hl) + s1 * 32 + lane);
            float4 t2 = __ldg(reinterpret_cast<const float4*>(hl) + s2 * 32 + lane);
            float4 t3 = __ldg(reinterpret_cast<const float4*>(hl) + s3 * 32 + lane);
            hv0[0]=t0.x; hv0[1]=t0.y; hv0[2]=t0.z; hv0[3]=t0.w;
            hv1[0]=t1.x; hv1[1]=t1.y; hv1[2]=t1.z; hv1[3]=t1.w;
            hv2[0]=t2.x; hv2[1]=t2.y; hv2[2]=t2.z; hv2[3]=t2.w;
            hv3[0]=t3.x; hv3[1]=t3.y; hv3[2]=t3.z; hv3[3]=t3.w;
        } else {
            float2 t0 = __ldg(reinterpret_cast<const float2*>(hl) + s0 * 32 + lane);
            float2 t1 = __ldg(reinterpret_cast<const float2*>(hl) + s1 * 32 + lane);
            float2 t2 = __ldg(reinterpret_cast<const float2*>(hl) + s2 * 32 + lane);
            float2 t3 = __ldg(reinterpret_cast<const float2*>(hl) + s3 * 32 + lane);
            hv0[0]=t0.x; hv0[1]=t0.y;
            hv1[0]=t1.x; hv1[1]=t1.y;
            hv2[0]=t2.x; hv2[1]=t2.y;
            hv3[0]=t3.x; hv3[1]=t3.y;
        }
        update(hv0); update(hv1); update(hv2); update(hv3);
    }
    for (; e < e1; e++) {
        int s = __ldg(&g_esrc[e]);
        float hv[V];
        if (V == 4) {
            float4 t = __ldg(reinterpret_cast<const float4*>(hl) + s * 32 + lane);
            hv[0]=t.x; hv[1]=t.y; hv[2]=t.z; hv[3]=t.w;
        } else {
            float2 t = __ldg(reinterpret_cast<const float2*>(hl) + s * 32 + lane);
            hv[0]=t.x; hv[1]=t.y;
        }
        update(hv);
    }

    float inv = 1.f / (lsum + 1e-16f);
    if (V == 4) {
        float4 o;
        o.x = fmaxf(fmaf(acc[0], inv, bias[lane * 4 + 0]), 0.f);
        o.y = fmaxf(fmaf(acc[1], inv, bias[lane * 4 + 1]), 0.f);
        o.z = fmaxf(fmaf(acc[2], inv, bias[lane * 4 + 2]), 0.f);
        o.w = fmaxf(fmaf(acc[3], inv, bias[lane * 4 + 3]), 0.f);
        reinterpret_cast<float4*>(out)[w * 32 + lane] = o;
    } else {
        float2 o;
        o.x = fmaxf(fmaf(acc[0], inv, bias[lane * 2 + 0]), 0.f);
        o.y = fmaxf(fmaf(acc[1], inv, bias[lane * 2 + 1]), 0.f);
        reinterpret_cast<float2*>(out)[w * 32 + lane] = o;
    }
}

// ---------------- launch ----------------
extern "C" void kernel_launch(void* const* d_in, const int* in_sizes, int n_in,
                              void* d_out, int out_size)
{
    const float* x   = (const float*)d_in[0];
    const void*  ei  = d_in[1];
    const float *W0l = (const float*)d_in[2],  *W0r = (const float*)d_in[3];
    const float *a0  = (const float*)d_in[4],  *b0  = (const float*)d_in[5];
    const float *W1l = (const float*)d_in[6],  *W1r = (const float*)d_in[7];
    const float *a1  = (const float*)d_in[8],  *b1  = (const float*)d_in[9];
    const float *W2l = (const float*)d_in[10], *W2r = (const float*)d_in[11];
    const float *a2  = (const float*)d_in[12], *b2  = (const float*)d_in[13];
    float* out = (float*)d_out;

    void *p_hl, *p_hr, *p_h;
    cudaGetSymbolAddress(&p_hl, g_hl);
    cudaGetSymbolAddress(&p_hr, g_hr);
    cudaGetSymbolAddress(&p_h, g_h);
    float* hl = (float*)p_hl;
    float* hr = (float*)p_hr;
    float* h  = (float*)p_h;

    const int eb = (ET + 255) / 256;
    const dim3 gg((NN + BM - 1) / BM, 2);
    const dim3 gg2((NN + BM - 1) / BM, 1);
    const int egrid = (NN * 32 + 255) / 256;

    // CSR prelude: exactly 5 launches so launch #6 (ncu -s 5 -c 1) is gemm_tf32_k
    zero_detect_k<<<(NN + 1023) / 1024, 1024>>>((const int*)ei);   // 1
    convert_count_k<<<eb, 256>>>(ei);                              // 2
    scan1_k<<<NB, 1024>>>();                                       // 3
    scan2_k<<<1, 32>>>();                                          // 4
    scan3_k<<<(NN + 255) / 256, 256>>>();                          // 5

    // layer 0 GEMMs (independent of scatter)
    gemm_tf32_k<<<gg, 256>>>(x, W0l, hl, NN, 128);                 // 6 <- profiled
    gemm_tf32_k<<<gg, 256>>>(x, W0r, hr, NN, 128);                 // 7
    scatter_k<<<eb, 256>>>();                                      // 8
    gat_edge<4, 128><<<egrid, 256>>>(hl, hr, a0, b0, h);           // 9
    // layer 1
    gemm_tf32_k<<<gg, 256>>>(h, W1l, hl, NN, 128);
    gemm_tf32_k<<<gg, 256>>>(h, W1r, hr, NN, 128);
    gat_edge<4, 128><<<egrid, 256>>>(hl, hr, a1, b1, h);
    // layer 2
    gemm_tf32_k<<<gg2, 256>>>(h, W2l, hl, NN, 64);
    gemm_tf32_k<<<gg2, 256>>>(h, W2r, hr, NN, 64);
    gat_edge<1, 64><<<egrid, 256>>>(hl, hr, a2, b2, out);
}

// round 4
// speedup vs baseline: 1.2428x; 1.0148x over previous
#include <cuda_runtime.h>
#include <math.h>

#define NN 100000
#define NE 1600000
#define ET 1700000          // NE + NN self loops
#define NB 98               // ceil(NN/1024)

// GEMM tiling
#define BM 128
#define BN 64
#define BK 16
#define AP 20               // A smem pitch ([m][k])
#define BP 72               // B smem pitch ([k][n])

// ---------------- static scratch (no allocations allowed) ----------------
__device__ __align__(256) float g_hl[NN * 128];
__device__ __align__(256) float g_hr[NN * 128];
__device__ __align__(256) float g_h [NN * 128];
__device__ int g_deg[NN];
__device__ int g_tmp[NN];
__device__ int g_rowptr[NN + 1];
__device__ int g_fill[NN];
__device__ int g_esrc[ET];
__device__ int g_src[ET];
__device__ int g_dst[ET];
__device__ int g_bsums[128];
__device__ int g_is64;

// ---------------- ingestion + CSR ----------------
__global__ void zero_detect_k(const int* __restrict__ ei32) {
    int i = blockIdx.x * blockDim.x + threadIdx.x;
    if (i < NN) g_deg[i] = 0;
    if (i == 0) {
        int acc = 0;
        for (int j = 0; j < 1024; j++) acc |= ei32[2 * j + 1];
        g_is64 = (acc == 0) ? 1 : 0;   // int64 little-endian => high words all 0
    }
}

__global__ void convert_count_k(const void* __restrict__ ei) {
    int i = blockIdx.x * blockDim.x + threadIdx.x;
    if (i >= ET) return;
    int s, d;
    if (i < NE) {
        if (g_is64) {
            s = (int)((const long long*)ei)[i];
            d = (int)((const long long*)ei)[NE + i];
        } else {
            s = ((const int*)ei)[i];
            d = ((const int*)ei)[NE + i];
        }
    } else {
        s = d = i - NE;                       // appended self loops
    }
    s = min(max(s, 0), NN - 1);               // defensive: never fault
    d = min(max(d, 0), NN - 1);
    g_src[i] = s;
    g_dst[i] = d;
    atomicAdd(&g_deg[d], 1);
}

__global__ void scan1_k() {
    __shared__ int sh[1024];
    int i = blockIdx.x * 1024 + threadIdx.x;
    int v = (i < NN) ? g_deg[i] : 0;
    sh[threadIdx.x] = v;
    __syncthreads();
    for (int off = 1; off < 1024; off <<= 1) {
        int t = (threadIdx.x >= off) ? sh[threadIdx.x - off] : 0;
        __syncthreads();
        sh[threadIdx.x] += t;
        __syncthreads();
    }
    if (i < NN) g_tmp[i] = sh[threadIdx.x];
    if (threadIdx.x == 1023) g_bsums[blockIdx.x] = sh[1023];
}

// fused scan2+scan3: each block redundantly prefix-sums the 98 block sums
__global__ void scan3_k() {
    __shared__ int pref[NB + 1];
    if (threadIdx.x == 0) {
        int acc = 0;
        for (int b = 0; b < NB; b++) { pref[b] = acc; acc += g_bsums[b]; }
    }
    __syncthreads();
    int i = blockIdx.x * blockDim.x + threadIdx.x;
    if (i < NN) {
        int incl = g_tmp[i] + pref[i >> 10];
        g_rowptr[i + 1] = incl;
        g_fill[i] = incl - g_deg[i];           // exclusive prefix = fill cursor
    }
    if (i == 0) g_rowptr[0] = 0;
}

__global__ void scatter_k() {
    int i = blockIdx.x * blockDim.x + threadIdx.x;
    if (i >= ET) return;
    int pos = atomicAdd(&g_fill[g_dst[i]], 1);
    g_esrc[pos] = g_src[i];
}

// ---------------- tf32x3 dual tensor-core GEMM ----------------
__device__ __forceinline__ unsigned f2tf(float x) {
    unsigned u;
    asm("cvt.rna.tf32.f32 %0, %1;" : "=r"(u) : "f"(x));
    return u;
}

__device__ __forceinline__ void mma8(float* c, const unsigned* a, const unsigned* b) {
    asm volatile(
        "mma.sync.aligned.m16n8k8.row.col.f32.tf32.tf32.f32 "
        "{%0,%1,%2,%3}, {%4,%5,%6,%7}, {%8,%9}, {%0,%1,%2,%3};"
        : "+f"(c[0]), "+f"(c[1]), "+f"(c[2]), "+f"(c[3])
        : "r"(a[0]), "r"(a[1]), "r"(a[2]), "r"(a[3]), "r"(b[0]), "r"(b[1]));
}

// Computes Cl = A@Wl and Cr = A@Wr in one pass (shared A tile + conversion).
__global__ __launch_bounds__(256) void gemm_dual_k(
    const float* __restrict__ A,
    const float* __restrict__ Wl, const float* __restrict__ Wr,
    float* __restrict__ Cl, float* __restrict__ Cr, int n, int oc)
{
    __shared__ unsigned Ah[BM * AP], Al[BM * AP];
    __shared__ unsigned Bh[2][BK * BP], Bl[2][BK * BP];

    const int tid = threadIdx.x;
    const int lane = tid & 31, wid = tid >> 5;
    const int wm = wid >> 1, wn = wid & 1;       // 4 x 2 warp grid
    const int gid = lane >> 2, tig = lane & 3;
    const int row0 = blockIdx.x * BM;
    const int col0 = blockIdx.y * BN;

    float acc[2][2][4][4];                        // [side][i][j][reg]
#pragma unroll
    for (int sd = 0; sd < 2; sd++)
#pragma unroll
        for (int i = 0; i < 2; i++)
#pragma unroll
            for (int j = 0; j < 4; j++)
#pragma unroll
                for (int r = 0; r < 4; r++) acc[sd][i][j][r] = 0.f;

    const int ar = tid >> 1, ah_half = (tid & 1) * 8;      // A: 128 rows x 16 k
    const int br = tid >> 4, bc = (tid & 15) * 4;          // B: 16 rows x 64 n

    for (int kk = 0; kk < 128; kk += BK) {
        // A tile -> smem (hi/lo split)
        {
            float v[8];
            if (row0 + ar < n) {
                float4 v0 = *reinterpret_cast<const float4*>(A + (row0 + ar) * 128 + kk + ah_half);
                float4 v1 = *reinterpret_cast<const float4*>(A + (row0 + ar) * 128 + kk + ah_half + 4);
                v[0] = v0.x; v[1] = v0.y; v[2] = v0.z; v[3] = v0.w;
                v[4] = v1.x; v[5] = v1.y; v[6] = v1.z; v[7] = v1.w;
            } else {
#pragma unroll
                for (int q = 0; q < 8; q++) v[q] = 0.f;
            }
#pragma unroll
            for (int q = 0; q < 8; q++) {
                unsigned hi = f2tf(v[q]);
                float lo = v[q] - __uint_as_float(hi);
                Ah[ar * AP + ah_half + q] = hi;
                Al[ar * AP + ah_half + q] = f2tf(lo);
            }
        }
        // B tiles (Wl and Wr) -> smem (hi/lo split)
        {
            const float* Ws[2] = {Wl, Wr};
#pragma unroll
            for (int sd = 0; sd < 2; sd++) {
                float4 v = *reinterpret_cast<const float4*>(Ws[sd] + (kk + br) * oc + col0 + bc);
                float b4[4] = {v.x, v.y, v.z, v.w};
#pragma unroll
                for (int q = 0; q < 4; q++) {
                    unsigned hi = f2tf(b4[q]);
                    float lo = b4[q] - __uint_as_float(hi);
                    Bh[sd][br * BP + bc + q] = hi;
                    Bl[sd][br * BP + bc + q] = f2tf(lo);
                }
            }
        }
        __syncthreads();

#pragma unroll
        for (int ks = 0; ks < 2; ks++) {
            const int k0 = ks * 8;
            unsigned ah[2][4], al[2][4];
#pragma unroll
            for (int i = 0; i < 2; i++) {
                int m0 = wm * 32 + i * 16;
                ah[i][0] = Ah[(m0 + gid) * AP + k0 + tig];
                ah[i][1] = Ah[(m0 + gid + 8) * AP + k0 + tig];
                ah[i][2] = Ah[(m0 + gid) * AP + k0 + tig + 4];
                ah[i][3] = Ah[(m0 + gid + 8) * AP + k0 + tig + 4];
                al[i][0] = Al[(m0 + gid) * AP + k0 + tig];
                al[i][1] = Al[(m0 + gid + 8) * AP + k0 + tig];
                al[i][2] = Al[(m0 + gid) * AP + k0 + tig + 4];
                al[i][3] = Al[(m0 + gid + 8) * AP + k0 + tig + 4];
            }
#pragma unroll
            for (int sd = 0; sd < 2; sd++) {
#pragma unroll
                for (int j = 0; j < 4; j++) {
                    int c = wn * 32 + j * 8 + gid;
                    unsigned bh[2], bl[2];
                    bh[0] = Bh[sd][(k0 + tig) * BP + c];
                    bh[1] = Bh[sd][(k0 + tig + 4) * BP + c];
                    bl[0] = Bl[sd][(k0 + tig) * BP + c];
                    bl[1] = Bl[sd][(k0 + tig + 4) * BP + c];
#pragma unroll
                    for (int i = 0; i < 2; i++) {
                        mma8(acc[sd][i][j], ah[i], bh);
                        mma8(acc[sd][i][j], ah[i], bl);
                        mma8(acc[sd][i][j], al[i], bh);
                    }
                }
            }
        }
        __syncthreads();
    }

    float* Cs[2] = {Cl, Cr};
#pragma unroll
    for (int sd = 0; sd < 2; sd++)
#pragma unroll
        for (int i = 0; i < 2; i++) {
            int rbase = row0 + wm * 32 + i * 16 + gid;
#pragma unroll
            for (int j = 0; j < 4; j++) {
                int c = col0 + wn * 32 + j * 8 + 2 * tig;
                if (rbase < n)
                    *reinterpret_cast<float2*>(Cs[sd] + rbase * oc + c) =
                        make_float2(acc[sd][i][j][0], acc[sd][i][j][1]);
                if (rbase + 8 < n)
                    *reinterpret_cast<float2*>(Cs[sd] + (rbase + 8) * oc + c) =
                        make_float2(acc[sd][i][j][2], acc[sd][i][j][3]);
            }
        }
}

// ---------------- fused edge kernel: segment softmax + aggregate ----------
// One warp per destination node. Self-loop score used as softmax offset
// (cancels exactly in alpha = w/sum), so no serial max-rescale chain.
template <int H, int CH>
__global__ __launch_bounds__(256) void gat_edge(
    const float* __restrict__ hl, const float* __restrict__ hr,
    const float* __restrict__ att, const float* __restrict__ bias,
    float* __restrict__ out)
{
    constexpr int V = CH / 32;
    const int w = (blockIdx.x * blockDim.x + threadIdx.x) >> 5;
    const int lane = threadIdx.x & 31;
    if (w >= NN) return;

    float attv[V], hrv[V], acc[V];
#pragma unroll
    for (int v = 0; v < V; v++) attv[v] = att[lane * V + v];

    if (V == 4) {
        float4 t = __ldg(reinterpret_cast<const float4*>(hr) + w * 32 + lane);
        hrv[0] = t.x; hrv[1] = t.y; hrv[2] = t.z; hrv[3] = t.w;
    } else {
        float2 t = __ldg(reinterpret_cast<const float2*>(hr) + w * 32 + lane);
        hrv[0] = t.x; hrv[1] = t.y;
    }
#pragma unroll
    for (int v = 0; v < V; v++) acc[v] = 0.f;

    // raw attention score for a gathered feature vector
    auto score = [&](const float* hv) {
        float p = 0.f;
#pragma unroll
        for (int v = 0; v < V; v++) {
            float t = hv[v] + hrv[v];
            t = (t > 0.f) ? t : 0.2f * t;          // LeakyReLU(0.2)
            p = fmaf(t, attv[v], p);
        }
#pragma unroll
        for (int off = (32 / H) >> 1; off > 0; off >>= 1)
            p += __shfl_xor_sync(0xffffffffu, p, off);
        return p;
    };

    // softmax offset = self-loop score (bounded vs any edge score; exp-safe)
    float p_self;
    {
        float hs[V];
        if (V == 4) {
            float4 t = __ldg(reinterpret_cast<const float4*>(hl) + w * 32 + lane);
            hs[0]=t.x; hs[1]=t.y; hs[2]=t.z; hs[3]=t.w;
        } else {
            float2 t = __ldg(reinterpret_cast<const float2*>(hl) + w * 32 + lane);
            hs[0]=t.x; hs[1]=t.y;
        }
        p_self = score(hs);
    }

    float lsum = 0.f;
    const int e0 = g_rowptr[w], e1 = g_rowptr[w + 1];

    auto update = [&](const float* hv) {
        float p = score(hv);
        float ww = __expf(p - p_self);
        lsum += ww;
#pragma unroll
        for (int v = 0; v < V; v++) acc[v] = fmaf(ww, hv[v], acc[v]);
    };

    int e = e0;
    for (; e + 4 <= e1; e += 4) {
        int s0 = __ldg(&g_esrc[e]);
        int s1 = __ldg(&g_esrc[e + 1]);
        int s2 = __ldg(&g_esrc[e + 2]);
        int s3 = __ldg(&g_esrc[e + 3]);
        float hv0[V], hv1[V], hv2[V], hv3[V];
        if (V == 4) {
            float4 t0 = __ldg(reinterpret_cast<const float4*>(hl) + s0 * 32 + lane);
            float4 t1 = __ldg(reinterpret_cast<const float4*>(hl) + s1 * 32 + lane);
            float4 t2 = __ldg(reinterpret_cast<const float4*>(hl) + s2 * 32 + lane);
            float4 t3 = __ldg(reinterpret_cast<const float4*>(hl) + s3 * 32 + lane);
            hv0[0]=t0.x; hv0[1]=t0.y; hv0[2]=t0.z; hv0[3]=t0.w;
            hv1[0]=t1.x; hv1[1]=t1.y; hv1[2]=t1.z; hv1[3]=t1.w;
            hv2[0]=t2.x; hv2[1]=t2.y; hv2[2]=t2.z; hv2[3]=t2.w;
            hv3[0]=t3.x; hv3[1]=t3.y; hv3[2]=t3.z; hv3[3]=t3.w;
        } else {
            float2 t0 = __ldg(reinterpret_cast<const float2*>(hl) + s0 * 32 + lane);
            float2 t1 = __ldg(reinterpret_cast<const float2*>(hl) + s1 * 32 + lane);
            float2 t2 = __ldg(reinterpret_cast<const float2*>(hl) + s2 * 32 + lane);
            float2 t3 = __ldg(reinterpret_cast<const float2*>(hl) + s3 * 32 + lane);
            hv0[0]=t0.x; hv0[1]=t0.y;
            hv1[0]=t1.x; hv1[1]=t1.y;
            hv2[0]=t2.x; hv2[1]=t2.y;
            hv3[0]=t3.x; hv3[1]=t3.y;
        }
        update(hv0); update(hv1); update(hv2); update(hv3);
    }
    for (; e < e1; e++) {
        int s = __ldg(&g_esrc[e]);
        float hv[V];
        if (V == 4) {
            float4 t = __ldg(reinterpret_cast<const float4*>(hl) + s * 32 + lane);
            hv[0]=t.x; hv[1]=t.y; hv[2]=t.z; hv[3]=t.w;
        } else {
            float2 t = __ldg(reinterpret_cast<const float2*>(hl) + s * 32 + lane);
            hv[0]=t.x; hv[1]=t.y;
        }
        update(hv);
    }

    float inv = 1.f / (lsum + 1e-16f);
    if (V == 4) {
        float4 o;
        o.x = fmaxf(fmaf(acc[0], inv, bias[lane * 4 + 0]), 0.f);
        o.y = fmaxf(fmaf(acc[1], inv, bias[lane * 4 + 1]), 0.f);
        o.z = fmaxf(fmaf(acc[2], inv, bias[lane * 4 + 2]), 0.f);
        o.w = fmaxf(fmaf(acc[3], inv, bias[lane * 4 + 3]), 0.f);
        reinterpret_cast<float4*>(out)[w * 32 + lane] = o;
    } else {
        float2 o;
        o.x = fmaxf(fmaf(acc[0], inv, bias[lane * 2 + 0]), 0.f);
        o.y = fmaxf(fmaf(acc[1], inv, bias[lane * 2 + 1]), 0.f);
        reinterpret_cast<float2*>(out)[w * 32 + lane] = o;
    }
}

// ---------------- launch ----------------
extern "C" void kernel_launch(void* const* d_in, const int* in_sizes, int n_in,
                              void* d_out, int out_size)
{
    const float* x   = (const float*)d_in[0];
    const void*  ei  = d_in[1];
    const float *W0l = (const float*)d_in[2],  *W0r = (const float*)d_in[3];
    const float *a0  = (const float*)d_in[4],  *b0  = (const float*)d_in[5];
    const float *W1l = (const float*)d_in[6],  *W1r = (const float*)d_in[7];
    const float *a1  = (const float*)d_in[8],  *b1  = (const float*)d_in[9];
    const float *W2l = (const float*)d_in[10], *W2r = (const float*)d_in[11];
    const float *a2  = (const float*)d_in[12], *b2  = (const float*)d_in[13];
    float* out = (float*)d_out;

    void *p_hl, *p_hr, *p_h;
    cudaGetSymbolAddress(&p_hl, g_hl);
    cudaGetSymbolAddress(&p_hr, g_hr);
    cudaGetSymbolAddress(&p_h, g_h);
    float* hl = (float*)p_hl;
    float* hr = (float*)p_hr;
    float* h  = (float*)p_h;

    const int eb = (ET + 255) / 256;
    const dim3 gg((NN + BM - 1) / BM, 2);
    const dim3 gg2((NN + BM - 1) / BM, 1);
    const int egrid = (NN * 32 + 255) / 256;

    zero_detect_k<<<(NN + 1023) / 1024, 1024>>>((const int*)ei);     // 1
    convert_count_k<<<eb, 256>>>(ei);                                // 2
    scan1_k<<<NB, 1024>>>();                                         // 3
    gemm_dual_k<<<gg, 256>>>(x, W0l, W0r, hl, hr, NN, 128);          // 4 <- profiled
    scan3_k<<<(NN + 255) / 256, 256>>>();                            // 5
    scatter_k<<<eb, 256>>>();                                        // 6
    gat_edge<4, 128><<<egrid, 256>>>(hl, hr, a0, b0, h);             // 7
    gemm_dual_k<<<gg, 256>>>(h, W1l, W1r, hl, hr, NN, 128);          // 8
    gat_edge<4, 128><<<egrid, 256>>>(hl, hr, a1, b1, h);             // 9
    gemm_dual_k<<<gg2, 256>>>(h, W2l, W2r, hl, hr, NN, 64);          // 10
    gat_edge<1, 64><<<egrid, 256>>>(hl, hr, a2, b2, out);            // 11
}

// round 5
// speedup vs baseline: 1.6135x; 1.2983x over previous
#include <cuda_runtime.h>
#include <math.h>

#define NN 100000
#define NE 1600000
#define ET 1700000          // NE + NN self loops
#define NB 98               // ceil(NN/1024)

// GEMM tiling
#define BM 128
#define BN 64
#define BK 16
#define AP 20               // A smem pitch (floats), conflict-free
#define BP 72               // B smem pitch (floats), conflict-free

// ---------------- static scratch (no allocations allowed) ----------------
__device__ __align__(256) float g_hl[NN * 128];
__device__ __align__(256) float g_hr[NN * 128];
__device__ __align__(256) float g_h [NN * 128];
__device__ int g_deg[NN];
__device__ int g_tmp[NN];
__device__ int g_rowptr[NN + 1];
__device__ int g_fill[NN];
__device__ int g_esrc[ET];
__device__ int g_src[ET];
__device__ int g_dst[ET];
__device__ int g_bsums[128];
__device__ int g_is64;

// ---------------- ingestion + CSR ----------------
__global__ void zero_detect_k(const int* __restrict__ ei32) {
    int i = blockIdx.x * blockDim.x + threadIdx.x;
    if (i < NN) g_deg[i] = 0;
    if (i == 0) {
        int acc = 0;
        for (int j = 0; j < 1024; j++) acc |= ei32[2 * j + 1];
        g_is64 = (acc == 0) ? 1 : 0;   // int64 little-endian => high words all 0
    }
}

__global__ void convert_count_k(const void* __restrict__ ei) {
    int i = blockIdx.x * blockDim.x + threadIdx.x;
    if (i >= ET) return;
    int s, d;
    if (i < NE) {
        if (g_is64) {
            s = (int)((const long long*)ei)[i];
            d = (int)((const long long*)ei)[NE + i];
        } else {
            s = ((const int*)ei)[i];
            d = ((const int*)ei)[NE + i];
        }
    } else {
        s = d = i - NE;                       // appended self loops
    }
    s = min(max(s, 0), NN - 1);               // defensive: never fault
    d = min(max(d, 0), NN - 1);
    g_src[i] = s;
    g_dst[i] = d;
    atomicAdd(&g_deg[d], 1);
}

__global__ void scan1_k() {
    __shared__ int sh[1024];
    int i = blockIdx.x * 1024 + threadIdx.x;
    int v = (i < NN) ? g_deg[i] : 0;
    sh[threadIdx.x] = v;
    __syncthreads();
    for (int off = 1; off < 1024; off <<= 1) {
        int t = (threadIdx.x >= off) ? sh[threadIdx.x - off] : 0;
        __syncthreads();
        sh[threadIdx.x] += t;
        __syncthreads();
    }
    if (i < NN) g_tmp[i] = sh[threadIdx.x];
    if (threadIdx.x == 1023) g_bsums[blockIdx.x] = sh[1023];
}

// fused scan2+scan3
__global__ void scan3_k() {
    __shared__ int pref[NB + 1];
    if (threadIdx.x == 0) {
        int acc = 0;
        for (int b = 0; b < NB; b++) { pref[b] = acc; acc += g_bsums[b]; }
    }
    __syncthreads();
    int i = blockIdx.x * blockDim.x + threadIdx.x;
    if (i < NN) {
        int incl = g_tmp[i] + pref[i >> 10];
        g_rowptr[i + 1] = incl;
        g_fill[i] = incl - g_deg[i];           // exclusive prefix = fill cursor
    }
    if (i == 0) g_rowptr[0] = 0;
}

__global__ void scatter_k() {
    int i = blockIdx.x * blockDim.x + threadIdx.x;
    if (i >= ET) return;
    int pos = atomicAdd(&g_fill[g_dst[i]], 1);
    g_esrc[pos] = g_src[i];
}

// ---------------- tf32x3 dual tensor-core GEMM ----------------
__device__ __forceinline__ unsigned f2tf(float x) {
    unsigned u;
    asm("cvt.rna.tf32.f32 %0, %1;" : "=r"(u) : "f"(x));
    return u;
}

__device__ __forceinline__ void mma8(float* c, const unsigned* a, const unsigned* b) {
    asm volatile(
        "mma.sync.aligned.m16n8k8.row.col.f32.tf32.tf32.f32 "
        "{%0,%1,%2,%3}, {%4,%5,%6,%7}, {%8,%9}, {%0,%1,%2,%3};"
        : "+f"(c[0]), "+f"(c[1]), "+f"(c[2]), "+f"(c[3])
        : "r"(a[0]), "r"(a[1]), "r"(a[2]), "r"(a[3]), "r"(b[0]), "r"(b[1]));
}

__device__ __forceinline__ void cp16(unsigned dst, const void* src, int srcBytes) {
    asm volatile("cp.async.ca.shared.global [%0], [%1], 16, %2;"
                 :: "r"(dst), "l"(src), "r"(srcBytes));
}

// Cl = A@Wl, Cr = A@Wr. Raw-fp32 double-buffered smem, cp.async pipeline,
// tf32x3 split done at fragment-load time.
__global__ __launch_bounds__(256, 2) void gemm_dual_k(
    const float* __restrict__ A,
    const float* __restrict__ Wl, const float* __restrict__ Wr,
    float* __restrict__ Cl, float* __restrict__ Cr, int n, int oc)
{
    __shared__ float As[2][BM * AP];
    __shared__ float Bs[2][2][BK * BP];

    const int tid = threadIdx.x;
    const int lane = tid & 31, wid = tid >> 5;
    const int wm = wid >> 1, wn = wid & 1;       // 4 x 2 warp grid
    const int gid = lane >> 2, tig = lane & 3;
    const int row0 = blockIdx.x * BM;
    const int col0 = blockIdx.y * BN;

    float acc[2][2][4][4];                        // [side][i][j][reg]
#pragma unroll
    for (int sd = 0; sd < 2; sd++)
#pragma unroll
        for (int i = 0; i < 2; i++)
#pragma unroll
            for (int j = 0; j < 4; j++)
#pragma unroll
                for (int r = 0; r < 4; r++) acc[sd][i][j][r] = 0.f;

    // per-thread copy assignments
    const int ar = tid >> 1, kof = (tid & 1) * 8;          // A: 2 x 16B per thread
    const int br = tid >> 4, bc = (tid & 15) * 4;          // B: 1 x 16B per side
    const int aValid = (row0 + ar < n) ? 16 : 0;

    auto load_stage = [&](int st, int kk) {
        const float* srcA = A + (size_t)(row0 + ar) * 128 + kk + kof;
        unsigned dA = (unsigned)__cvta_generic_to_shared(&As[st][ar * AP + kof]);
        cp16(dA, srcA, aValid);
        cp16(dA + 16, srcA + 4, aValid);
        cp16((unsigned)__cvta_generic_to_shared(&Bs[st][0][br * BP + bc]),
             Wl + (size_t)(kk + br) * oc + col0 + bc, 16);
        cp16((unsigned)__cvta_generic_to_shared(&Bs[st][1][br * BP + bc]),
             Wr + (size_t)(kk + br) * oc + col0 + bc, 16);
    };

    load_stage(0, 0);
    asm volatile("cp.async.commit_group;");

#pragma unroll
    for (int it = 0; it < 8; it++) {
        const int buf = it & 1;
        if (it + 1 < 8) {
            load_stage(buf ^ 1, (it + 1) * BK);
            asm volatile("cp.async.commit_group;");
            asm volatile("cp.async.wait_group 1;");
        } else {
            asm volatile("cp.async.wait_group 0;");
        }
        __syncthreads();

#pragma unroll
        for (int ks = 0; ks < 2; ks++) {
            const int k0 = ks * 8;
            unsigned ah[2][4], al[2][4];
#pragma unroll
            for (int i = 0; i < 2; i++) {
                const int m0 = wm * 32 + i * 16;
                float a0 = As[buf][(m0 + gid) * AP + k0 + tig];
                float a1 = As[buf][(m0 + gid + 8) * AP + k0 + tig];
                float a2 = As[buf][(m0 + gid) * AP + k0 + tig + 4];
                float a3 = As[buf][(m0 + gid + 8) * AP + k0 + tig + 4];
                ah[i][0] = f2tf(a0); al[i][0] = f2tf(a0 - __uint_as_float(ah[i][0]));
                ah[i][1] = f2tf(a1); al[i][1] = f2tf(a1 - __uint_as_float(ah[i][1]));
                ah[i][2] = f2tf(a2); al[i][2] = f2tf(a2 - __uint_as_float(ah[i][2]));
                ah[i][3] = f2tf(a3); al[i][3] = f2tf(a3 - __uint_as_float(ah[i][3]));
            }
#pragma unroll
            for (int sd = 0; sd < 2; sd++) {
#pragma unroll
                for (int j = 0; j < 4; j++) {
                    const int c = wn * 32 + j * 8 + gid;
                    float b0 = Bs[buf][sd][(k0 + tig) * BP + c];
                    float b1 = Bs[buf][sd][(k0 + tig + 4) * BP + c];
                    unsigned bh[2], bl[2];
                    bh[0] = f2tf(b0); bl[0] = f2tf(b0 - __uint_as_float(bh[0]));
                    bh[1] = f2tf(b1); bl[1] = f2tf(b1 - __uint_as_float(bh[1]));
#pragma unroll
                    for (int i = 0; i < 2; i++) {
                        mma8(acc[sd][i][j], ah[i], bh);
                        mma8(acc[sd][i][j], ah[i], bl);
                        mma8(acc[sd][i][j], al[i], bh);
                    }
                }
            }
        }
        __syncthreads();
    }

    float* Cs[2] = {Cl, Cr};
#pragma unroll
    for (int sd = 0; sd < 2; sd++)
#pragma unroll
        for (int i = 0; i < 2; i++) {
            int rbase = row0 + wm * 32 + i * 16 + gid;
#pragma unroll
            for (int j = 0; j < 4; j++) {
                int c = col0 + wn * 32 + j * 8 + 2 * tig;
                if (rbase < n)
                    *reinterpret_cast<float2*>(Cs[sd] + rbase * oc + c) =
                        make_float2(acc[sd][i][j][0], acc[sd][i][j][1]);
                if (rbase + 8 < n)
                    *reinterpret_cast<float2*>(Cs[sd] + (rbase + 8) * oc + c) =
                        make_float2(acc[sd][i][j][2], acc[sd][i][j][3]);
            }
        }
}

// ---------------- fused edge kernel: segment softmax + aggregate ----------
// One warp per destination node; self-loop score as fixed softmax offset.
template <int H, int CH>
__global__ __launch_bounds__(256) void gat_edge(
    const float* __restrict__ hl, const float* __restrict__ hr,
    const float* __restrict__ att, const float* __restrict__ bias,
    float* __restrict__ out)
{
    constexpr int V = CH / 32;
    const int w = (blockIdx.x * blockDim.x + threadIdx.x) >> 5;
    const int lane = threadIdx.x & 31;
    if (w >= NN) return;

    float attv[V], hrv[V], acc[V];
#pragma unroll
    for (int v = 0; v < V; v++) attv[v] = att[lane * V + v];

    if (V == 4) {
        float4 t = __ldg(reinterpret_cast<const float4*>(hr) + w * 32 + lane);
        hrv[0] = t.x; hrv[1] = t.y; hrv[2] = t.z; hrv[3] = t.w;
    } else {
        float2 t = __ldg(reinterpret_cast<const float2*>(hr) + w * 32 + lane);
        hrv[0] = t.x; hrv[1] = t.y;
    }
#pragma unroll
    for (int v = 0; v < V; v++) acc[v] = 0.f;

    auto score = [&](const float* hv) {
        float p = 0.f;
#pragma unroll
        for (int v = 0; v < V; v++) {
            float t = hv[v] + hrv[v];
            t = (t > 0.f) ? t : 0.2f * t;          // LeakyReLU(0.2)
            p = fmaf(t, attv[v], p);
        }
#pragma unroll
        for (int off = (32 / H) >> 1; off > 0; off >>= 1)
            p += __shfl_xor_sync(0xffffffffu, p, off);
        return p;
    };

    float p_self;
    {
        float hs[V];
        if (V == 4) {
            float4 t = __ldg(reinterpret_cast<const float4*>(hl) + w * 32 + lane);
            hs[0]=t.x; hs[1]=t.y; hs[2]=t.z; hs[3]=t.w;
        } else {
            float2 t = __ldg(reinterpret_cast<const float2*>(hl) + w * 32 + lane);
            hs[0]=t.x; hs[1]=t.y;
        }
        p_self = score(hs);
    }

    float lsum = 0.f;
    const int e0 = g_rowptr[w], e1 = g_rowptr[w + 1];

    auto update = [&](const float* hv) {
        float p = score(hv);
        float ww = __expf(p - p_self);
        lsum += ww;
#pragma unroll
        for (int v = 0; v < V; v++) acc[v] = fmaf(ww, hv[v], acc[v]);
    };

    int e = e0;
    for (; e + 4 <= e1; e += 4) {
        int s0 = __ldg(&g_esrc[e]);
        int s1 = __ldg(&g_esrc[e + 1]);
        int s2 = __ldg(&g_esrc[e + 2]);
        int s3 = __ldg(&g_esrc[e + 3]);
        float hv0[V], hv1[V], hv2[V], hv3[V];
        if (V == 4) {
            float4 t0 = __ldg(reinterpret_cast<const float4*>(hl) + s0 * 32 + lane);
            float4 t1 = __ldg(reinterpret_cast<const float4*>(hl) + s1 * 32 + lane);
            float4 t2 = __ldg(reinterpret_cast<const float4*>(hl) + s2 * 32 + lane);
            float4 t3 = __ldg(reinterpret_cast<const float4*>(hl) + s3 * 32 + lane);
            hv0[0]=t0.x; hv0[1]=t0.y; hv0[2]=t0.z; hv0[3]=t0.w;
            hv1[0]=t1.x; hv1[1]=t1.y; hv1[2]=t1.z; hv1[3]=t1.w;
            hv2[0]=t2.x; hv2[1]=t2.y; hv2[2]=t2.z; hv2[3]=t2.w;
            hv3[0]=t3.x; hv3[1]=t3.y; hv3[2]=t3.z; hv3[3]=t3.w;
        } else {
            float2 t0 = __ldg(reinterpret_cast<const float2*>(hl) + s0 * 32 + lane);
            float2 t1 = __ldg(reinterpret_cast<const float2*>(hl) + s1 * 32 + lane);
            float2 t2 = __ldg(reinterpret_cast<const float2*>(hl) + s2 * 32 + lane);
            float2 t3 = __ldg(reinterpret_cast<const float2*>(hl) + s3 * 32 + lane);
            hv0[0]=t0.x; hv0[1]=t0.y;
            hv1[0]=t1.x; hv1[1]=t1.y;
            hv2[0]=t2.x; hv2[1]=t2.y;
            hv3[0]=t3.x; hv3[1]=t3.y;
        }
        update(hv0); update(hv1); update(hv2); update(hv3);
    }
    for (; e < e1; e++) {
        int s = __ldg(&g_esrc[e]);
        float hv[V];
        if (V == 4) {
            float4 t = __ldg(reinterpret_cast<const float4*>(hl) + s * 32 + lane);
            hv[0]=t.x; hv[1]=t.y; hv[2]=t.z; hv[3]=t.w;
        } else {
            float2 t = __ldg(reinterpret_cast<const float2*>(hl) + s * 32 + lane);
            hv[0]=t.x; hv[1]=t.y;
        }
        update(hv);
    }

    float inv = 1.f / (lsum + 1e-16f);
    if (V == 4) {
        float4 o;
        o.x = fmaxf(fmaf(acc[0], inv, bias[lane * 4 + 0]), 0.f);
        o.y = fmaxf(fmaf(acc[1], inv, bias[lane * 4 + 1]), 0.f);
        o.z = fmaxf(fmaf(acc[2], inv, bias[lane * 4 + 2]), 0.f);
        o.w = fmaxf(fmaf(acc[3], inv, bias[lane * 4 + 3]), 0.f);
        reinterpret_cast<float4*>(out)[w * 32 + lane] = o;
    } else {
        float2 o;
        o.x = fmaxf(fmaf(acc[0], inv, bias[lane * 2 + 0]), 0.f);
        o.y = fmaxf(fmaf(acc[1], inv, bias[lane * 2 + 1]), 0.f);
        reinterpret_cast<float2*>(out)[w * 32 + lane] = o;
    }
}

// ---------------- launch ----------------
extern "C" void kernel_launch(void* const* d_in, const int* in_sizes, int n_in,
                              void* d_out, int out_size)
{
    const float* x   = (const float*)d_in[0];
    const void*  ei  = d_in[1];
    const float *W0l = (const float*)d_in[2],  *W0r = (const float*)d_in[3];
    const float *a0  = (const float*)d_in[4],  *b0  = (const float*)d_in[5];
    const float *W1l = (const float*)d_in[6],  *W1r = (const float*)d_in[7];
    const float *a1  = (const float*)d_in[8],  *b1  = (const float*)d_in[9];
    const float *W2l = (const float*)d_in[10], *W2r = (const float*)d_in[11];
    const float *a2  = (const float*)d_in[12], *b2  = (const float*)d_in[13];
    float* out = (float*)d_out;

    void *p_hl, *p_hr, *p_h;
    cudaGetSymbolAddress(&p_hl, g_hl);
    cudaGetSymbolAddress(&p_hr, g_hr);
    cudaGetSymbolAddress(&p_h, g_h);
    float* hl = (float*)p_hl;
    float* hr = (float*)p_hr;
    float* h  = (float*)p_h;

    const int eb = (ET + 255) / 256;
    const dim3 gg((NN + BM - 1) / BM, 2);
    const dim3 gg2((NN + BM - 1) / BM, 1);
    const int egrid = (NN * 32 + 255) / 256;

    zero_detect_k<<<(NN + 1023) / 1024, 1024>>>((const int*)ei);     // 1
    convert_count_k<<<eb, 256>>>(ei);                                // 2
    scan1_k<<<NB, 1024>>>();                                         // 3
    gemm_dual_k<<<gg, 256>>>(x, W0l, W0r, hl, hr, NN, 128);          // 4 <- profiled
    scan3_k<<<(NN + 255) / 256, 256>>>();                            // 5
    scatter_k<<<eb, 256>>>();                                        // 6
    gat_edge<4, 128><<<egrid, 256>>>(hl, hr, a0, b0, h);             // 7
    gemm_dual_k<<<gg, 256>>>(h, W1l, W1r, hl, hr, NN, 128);          // 8
    gat_edge<4, 128><<<egrid, 256>>>(hl, hr, a1, b1, h);             // 9
    gemm_dual_k<<<gg2, 256>>>(h, W2l, W2r, hl, hr, NN, 64);          // 10
    gat_edge<1, 64><<<egrid, 256>>>(hl, hr, a2, b2, out);            // 11
}

// round 6
// speedup vs baseline: 1.7112x; 1.0605x over previous
#include <cuda_runtime.h>
#include <cuda_fp16.h>
#include <math.h>

#define NN 100000
#define NE 1600000
#define ET 1700000          // NE + NN self loops
#define NB 98               // ceil(NN/1024)

// GEMM tiling
#define BM 128
#define BN 64
#define BK 16
#define AP 20               // A smem pitch (floats), conflict-free
#define BP 72               // B smem pitch (floats), conflict-free

// ---------------- static scratch (no allocations allowed) ----------------
__device__ __align__(256) __half g_hlh[NN * 128];   // hl in fp16 (gathered per edge)
__device__ __align__(256) float  g_hr[NN * 128];
__device__ __align__(256) float  g_h [NN * 128];
__device__ int g_deg[NN];
__device__ int g_tmp[NN];
__device__ int g_rowptr[NN + 1];
__device__ int g_fill[NN];
__device__ int g_esrc[ET];
__device__ int g_src[ET];
__device__ int g_dst[ET];
__device__ int g_bsums[128];
__device__ int g_is64;

// ---------------- ingestion + CSR ----------------
__global__ void zero_detect_k(const int* __restrict__ ei32) {
    int i = blockIdx.x * blockDim.x + threadIdx.x;
    if (i < NN) g_deg[i] = 0;
    if (i == 0) {
        int acc = 0;
        for (int j = 0; j < 1024; j++) acc |= ei32[2 * j + 1];
        g_is64 = (acc == 0) ? 1 : 0;   // int64 little-endian => high words all 0
    }
}

__global__ void convert_count_k(const void* __restrict__ ei) {
    int i = blockIdx.x * blockDim.x + threadIdx.x;
    if (i >= ET) return;
    int s, d;
    if (i < NE) {
        if (g_is64) {
            s = (int)((const long long*)ei)[i];
            d = (int)((const long long*)ei)[NE + i];
        } else {
            s = ((const int*)ei)[i];
            d = ((const int*)ei)[NE + i];
        }
    } else {
        s = d = i - NE;                       // appended self loops
    }
    s = min(max(s, 0), NN - 1);               // defensive: never fault
    d = min(max(d, 0), NN - 1);
    g_src[i] = s;
    g_dst[i] = d;
    atomicAdd(&g_deg[d], 1);
}

__global__ void scan1_k() {
    __shared__ int sh[1024];
    int i = blockIdx.x * 1024 + threadIdx.x;
    int v = (i < NN) ? g_deg[i] : 0;
    sh[threadIdx.x] = v;
    __syncthreads();
    for (int off = 1; off < 1024; off <<= 1) {
        int t = (threadIdx.x >= off) ? sh[threadIdx.x - off] : 0;
        __syncthreads();
        sh[threadIdx.x] += t;
        __syncthreads();
    }
    if (i < NN) g_tmp[i] = sh[threadIdx.x];
    if (threadIdx.x == 1023) g_bsums[blockIdx.x] = sh[1023];
}

// fused scan2+scan3
__global__ void scan3_k() {
    __shared__ int pref[NB + 1];
    if (threadIdx.x == 0) {
        int acc = 0;
        for (int b = 0; b < NB; b++) { pref[b] = acc; acc += g_bsums[b]; }
    }
    __syncthreads();
    int i = blockIdx.x * blockDim.x + threadIdx.x;
    if (i < NN) {
        int incl = g_tmp[i] + pref[i >> 10];
        g_rowptr[i + 1] = incl;
        g_fill[i] = incl - g_deg[i];           // exclusive prefix = fill cursor
    }
    if (i == 0) g_rowptr[0] = 0;
}

__global__ void scatter_k() {
    int i = blockIdx.x * blockDim.x + threadIdx.x;
    if (i >= ET) return;
    int pos = atomicAdd(&g_fill[g_dst[i]], 1);
    g_esrc[pos] = g_src[i];
}

// ---------------- tf32x3 dual tensor-core GEMM ----------------
__device__ __forceinline__ unsigned f2tf(float x) {
    unsigned u;
    asm("cvt.rna.tf32.f32 %0, %1;" : "=r"(u) : "f"(x));
    return u;
}

__device__ __forceinline__ void mma8(float* c, const unsigned* a, const unsigned* b) {
    asm volatile(
        "mma.sync.aligned.m16n8k8.row.col.f32.tf32.tf32.f32 "
        "{%0,%1,%2,%3}, {%4,%5,%6,%7}, {%8,%9}, {%0,%1,%2,%3};"
        : "+f"(c[0]), "+f"(c[1]), "+f"(c[2]), "+f"(c[3])
        : "r"(a[0]), "r"(a[1]), "r"(a[2]), "r"(a[3]), "r"(b[0]), "r"(b[1]));
}

__device__ __forceinline__ void cp16(unsigned dst, const void* src, int srcBytes) {
    asm volatile("cp.async.ca.shared.global [%0], [%1], 16, %2;"
                 :: "r"(dst), "l"(src), "r"(srcBytes));
}

// Cl(half) = A@Wl, Cr(float) = A@Wr. Double-buffered cp.async, tf32x3 at
// fragment load (lo residual passed raw: hw truncates to tf32 anyway).
__global__ __launch_bounds__(256, 2) void gemm_dual_k(
    const float* __restrict__ A,
    const float* __restrict__ Wl, const float* __restrict__ Wr,
    __half* __restrict__ Cl, float* __restrict__ Cr, int n, int oc)
{
    __shared__ float As[2][BM * AP];
    __shared__ float Bs[2][2][BK * BP];

    const int tid = threadIdx.x;
    const int lane = tid & 31, wid = tid >> 5;
    const int wm = wid >> 1, wn = wid & 1;       // 4 x 2 warp grid
    const int gid = lane >> 2, tig = lane & 3;
    const int row0 = blockIdx.x * BM;
    const int col0 = blockIdx.y * BN;

    float acc[2][2][4][4];                        // [side][i][j][reg]
#pragma unroll
    for (int sd = 0; sd < 2; sd++)
#pragma unroll
        for (int i = 0; i < 2; i++)
#pragma unroll
            for (int j = 0; j < 4; j++)
#pragma unroll
                for (int r = 0; r < 4; r++) acc[sd][i][j][r] = 0.f;

    const int ar = tid >> 1, kof = (tid & 1) * 8;          // A: 2 x 16B per thread
    const int br = tid >> 4, bc = (tid & 15) * 4;          // B: 1 x 16B per side
    const int aValid = (row0 + ar < n) ? 16 : 0;

    auto load_stage = [&](int st, int kk) {
        const float* srcA = A + (size_t)(row0 + ar) * 128 + kk + kof;
        unsigned dA = (unsigned)__cvta_generic_to_shared(&As[st][ar * AP + kof]);
        cp16(dA, srcA, aValid);
        cp16(dA + 16, srcA + 4, aValid);
        cp16((unsigned)__cvta_generic_to_shared(&Bs[st][0][br * BP + bc]),
             Wl + (size_t)(kk + br) * oc + col0 + bc, 16);
        cp16((unsigned)__cvta_generic_to_shared(&Bs[st][1][br * BP + bc]),
             Wr + (size_t)(kk + br) * oc + col0 + bc, 16);
    };

    load_stage(0, 0);
    asm volatile("cp.async.commit_group;");

#pragma unroll
    for (int it = 0; it < 8; it++) {
        const int buf = it & 1;
        if (it + 1 < 8) {
            load_stage(buf ^ 1, (it + 1) * BK);
            asm volatile("cp.async.commit_group;");
            asm volatile("cp.async.wait_group 1;");
        } else {
            asm volatile("cp.async.wait_group 0;");
        }
        __syncthreads();

#pragma unroll
        for (int ks = 0; ks < 2; ks++) {
            const int k0 = ks * 8;
            unsigned ah[2][4], al[2][4];
#pragma unroll
            for (int i = 0; i < 2; i++) {
                const int m0 = wm * 32 + i * 16;
                float a0 = As[buf][(m0 + gid) * AP + k0 + tig];
                float a1 = As[buf][(m0 + gid + 8) * AP + k0 + tig];
                float a2 = As[buf][(m0 + gid) * AP + k0 + tig + 4];
                float a3 = As[buf][(m0 + gid + 8) * AP + k0 + tig + 4];
                ah[i][0] = f2tf(a0); al[i][0] = __float_as_uint(a0 - __uint_as_float(ah[i][0]));
                ah[i][1] = f2tf(a1); al[i][1] = __float_as_uint(a1 - __uint_as_float(ah[i][1]));
                ah[i][2] = f2tf(a2); al[i][2] = __float_as_uint(a2 - __uint_as_float(ah[i][2]));
                ah[i][3] = f2tf(a3); al[i][3] = __float_as_uint(a3 - __uint_as_float(ah[i][3]));
            }
#pragma unroll
            for (int sd = 0; sd < 2; sd++) {
#pragma unroll
                for (int j = 0; j < 4; j++) {
                    const int c = wn * 32 + j * 8 + gid;
                    float b0 = Bs[buf][sd][(k0 + tig) * BP + c];
                    float b1 = Bs[buf][sd][(k0 + tig + 4) * BP + c];
                    unsigned bh[2], bl[2];
                    bh[0] = f2tf(b0); bl[0] = __float_as_uint(b0 - __uint_as_float(bh[0]));
                    bh[1] = f2tf(b1); bl[1] = __float_as_uint(b1 - __uint_as_float(bh[1]));
#pragma unroll
                    for (int i = 0; i < 2; i++) {
                        mma8(acc[sd][i][j], ah[i], bh);
                        mma8(acc[sd][i][j], ah[i], bl);
                        mma8(acc[sd][i][j], al[i], bh);
                    }
                }
            }
        }
        __syncthreads();
    }

#pragma unroll
    for (int i = 0; i < 2; i++) {
        int rbase = row0 + wm * 32 + i * 16 + gid;
#pragma unroll
        for (int j = 0; j < 4; j++) {
            int c = col0 + wn * 32 + j * 8 + 2 * tig;
            if (rbase < n) {
                *reinterpret_cast<__half2*>(Cl + (size_t)rbase * oc + c) =
                    __floats2half2_rn(acc[0][i][j][0], acc[0][i][j][1]);
                *reinterpret_cast<float2*>(Cr + (size_t)rbase * oc + c) =
                    make_float2(acc[1][i][j][0], acc[1][i][j][1]);
            }
            if (rbase + 8 < n) {
                *reinterpret_cast<__half2*>(Cl + (size_t)(rbase + 8) * oc + c) =
                    __floats2half2_rn(acc[0][i][j][2], acc[0][i][j][3]);
                *reinterpret_cast<float2*>(Cr + (size_t)(rbase + 8) * oc + c) =
                    make_float2(acc[1][i][j][2], acc[1][i][j][3]);
            }
        }
    }
}

// ---------------- fused edge kernel: segment softmax + aggregate ----------
// One warp per destination node; self-loop score as fixed softmax offset.
// hl gathered in fp16 (halves L2 traffic vs fp32).
template <int H, int CH>
__global__ __launch_bounds__(256) void gat_edge(
    const __half* __restrict__ hl, const float* __restrict__ hr,
    const float* __restrict__ att, const float* __restrict__ bias,
    float* __restrict__ out)
{
    constexpr int V = CH / 32;
    const int w = (blockIdx.x * blockDim.x + threadIdx.x) >> 5;
    const int lane = threadIdx.x & 31;
    if (w >= NN) return;

    float attv[V], hrv[V], acc[V];
#pragma unroll
    for (int v = 0; v < V; v++) attv[v] = att[lane * V + v];

    if (V == 4) {
        float4 t = __ldg(reinterpret_cast<const float4*>(hr) + w * 32 + lane);
        hrv[0] = t.x; hrv[1] = t.y; hrv[2] = t.z; hrv[3] = t.w;
    } else {
        float2 t = __ldg(reinterpret_cast<const float2*>(hr) + w * 32 + lane);
        hrv[0] = t.x; hrv[1] = t.y;
    }
#pragma unroll
    for (int v = 0; v < V; v++) acc[v] = 0.f;

    // gather fp16 features of node s into float hv[V]
    auto gather = [&](int s, float* hv) {
        if (V == 4) {
            uint2 t = __ldg(reinterpret_cast<const uint2*>(hl) + s * 32 + lane);
            float2 f01 = __half22float2(*reinterpret_cast<__half2*>(&t.x));
            float2 f23 = __half22float2(*reinterpret_cast<__half2*>(&t.y));
            hv[0] = f01.x; hv[1] = f01.y; hv[2] = f23.x; hv[3] = f23.y;
        } else {
            unsigned t = __ldg(reinterpret_cast<const unsigned*>(hl) + s * 32 + lane);
            float2 f = __half22float2(*reinterpret_cast<__half2*>(&t));
            hv[0] = f.x; hv[1] = f.y;
        }
    };

    auto score = [&](const float* hv) {
        float p = 0.f;
#pragma unroll
        for (int v = 0; v < V; v++) {
            float t = hv[v] + hrv[v];
            t = (t > 0.f) ? t : 0.2f * t;          // LeakyReLU(0.2)
            p = fmaf(t, attv[v], p);
        }
#pragma unroll
        for (int off = (32 / H) >> 1; off > 0; off >>= 1)
            p += __shfl_xor_sync(0xffffffffu, p, off);
        return p;
    };

    float p_self;
    {
        float hs[V];
        gather(w, hs);
        p_self = score(hs);
    }

    float lsum = 0.f;
    const int e0 = g_rowptr[w], e1 = g_rowptr[w + 1];

    auto update = [&](const float* hv) {
        float p = score(hv);
        float ww = __expf(p - p_self);
        lsum += ww;
#pragma unroll
        for (int v = 0; v < V; v++) acc[v] = fmaf(ww, hv[v], acc[v]);
    };

    int e = e0;
    for (; e + 4 <= e1; e += 4) {
        int s0 = __ldg(&g_esrc[e]);
        int s1 = __ldg(&g_esrc[e + 1]);
        int s2 = __ldg(&g_esrc[e + 2]);
        int s3 = __ldg(&g_esrc[e + 3]);
        float hv0[V], hv1[V], hv2[V], hv3[V];
        gather(s0, hv0); gather(s1, hv1); gather(s2, hv2); gather(s3, hv3);
        update(hv0); update(hv1); update(hv2); update(hv3);
    }
    for (; e < e1; e++) {
        int s = __ldg(&g_esrc[e]);
        float hv[V];
        gather(s, hv);
        update(hv);
    }

    float inv = 1.f / (lsum + 1e-16f);
    if (V == 4) {
        float4 o;
        o.x = fmaxf(fmaf(acc[0], inv, bias[lane * 4 + 0]), 0.f);
        o.y = fmaxf(fmaf(acc[1], inv, bias[lane * 4 + 1]), 0.f);
        o.z = fmaxf(fmaf(acc[2], inv, bias[lane * 4 + 2]), 0.f);
        o.w = fmaxf(fmaf(acc[3], inv, bias[lane * 4 + 3]), 0.f);
        reinterpret_cast<float4*>(out)[w * 32 + lane] = o;
    } else {
        float2 o;
        o.x = fmaxf(fmaf(acc[0], inv, bias[lane * 2 + 0]), 0.f);
        o.y = fmaxf(fmaf(acc[1], inv, bias[lane * 2 + 1]), 0.f);
        reinterpret_cast<float2*>(out)[w * 32 + lane] = o;
    }
}

// ---------------- launch ----------------
extern "C" void kernel_launch(void* const* d_in, const int* in_sizes, int n_in,
                              void* d_out, int out_size)
{
    const float* x   = (const float*)d_in[0];
    const void*  ei  = d_in[1];
    const float *W0l = (const float*)d_in[2],  *W0r = (const float*)d_in[3];
    const float *a0  = (const float*)d_in[4],  *b0  = (const float*)d_in[5];
    const float *W1l = (const float*)d_in[6],  *W1r = (const float*)d_in[7];
    const float *a1  = (const float*)d_in[8],  *b1  = (const float*)d_in[9];
    const float *W2l = (const float*)d_in[10], *W2r = (const float*)d_in[11];
    const float *a2  = (const float*)d_in[12], *b2  = (const float*)d_in[13];
    float* out = (float*)d_out;

    void *p_hlh, *p_hr, *p_h;
    cudaGetSymbolAddress(&p_hlh, g_hlh);
    cudaGetSymbolAddress(&p_hr, g_hr);
    cudaGetSymbolAddress(&p_h, g_h);
    __half* hl = (__half*)p_hlh;
    float*  hr = (float*)p_hr;
    float*  h  = (float*)p_h;

    const int eb = (ET + 255) / 256;
    const dim3 gg((NN + BM - 1) / BM, 2);
    const dim3 gg2((NN + BM - 1) / BM, 1);
    const int egrid = (NN * 32 + 255) / 256;

    zero_detect_k<<<(NN + 1023) / 1024, 1024>>>((const int*)ei);     // 1
    convert_count_k<<<eb, 256>>>(ei);                                // 2
    scan1_k<<<NB, 1024>>>();                                         // 3
    gemm_dual_k<<<gg, 256>>>(x, W0l, W0r, hl, hr, NN, 128);          // 4 <- profiled
    scan3_k<<<(NN + 255) / 256, 256>>>();                            // 5
    scatter_k<<<eb, 256>>>();                                        // 6
    gat_edge<4, 128><<<egrid, 256>>>(hl, hr, a0, b0, h);             // 7
    gemm_dual_k<<<gg, 256>>>(h, W1l, W1r, hl, hr, NN, 128);          // 8
    gat_edge<4, 128><<<egrid, 256>>>(hl, hr, a1, b1, h);             // 9
    gemm_dual_k<<<gg2, 256>>>(h, W2l, W2r, hl, hr, NN, 64);          // 10
    gat_edge<1, 64><<<egrid, 256>>>(hl, hr, a2, b2, out);            // 11
}

// round 8
// speedup vs baseline: 1.9384x; 1.1328x over previous
#include <cuda_runtime.h>
#include <cuda_fp16.h>
#include <math.h>

#define NN 100000
#define NE 1600000
#define ET 1700000          // NE + NN self loops
#define NB 98               // ceil(NN/1024)

// GEMM tiling
#define BM 128
#define BN 64
#define BK 16

// ---------------- static scratch (no allocations allowed) ----------------
__device__ __align__(256) __half g_hlh[NN * 128];   // hl in fp16 (gathered per edge)
__device__ __align__(256) float  g_hr[NN * 128];
__device__ __align__(256) float  g_h [NN * 128];
__device__ int g_deg[NN];
__device__ int g_tmp[NN];
__device__ int g_rowptr[NN + 1];
__device__ int g_fill[NN];
__device__ int g_esrc[ET];
__device__ int g_src[ET];
__device__ int g_dst[ET];
__device__ int g_bsums[128];
__device__ int g_is64;

// ---------------- ingestion + CSR ----------------
__global__ void zero_detect_k(const int* __restrict__ ei32) {
    int i = blockIdx.x * blockDim.x + threadIdx.x;
    if (i < NN) g_deg[i] = 0;
    if (i == 0) {
        int acc = 0;
        for (int j = 0; j < 1024; j++) acc |= ei32[2 * j + 1];
        g_is64 = (acc == 0) ? 1 : 0;   // int64 little-endian => high words all 0
    }
}

__global__ void convert_count_k(const void* __restrict__ ei) {
    int i = blockIdx.x * blockDim.x + threadIdx.x;
    if (i >= ET) return;
    int s, d;
    if (i < NE) {
        if (g_is64) {
            s = (int)((const long long*)ei)[i];
            d = (int)((const long long*)ei)[NE + i];
        } else {
            s = ((const int*)ei)[i];
            d = ((const int*)ei)[NE + i];
        }
    } else {
        s = d = i - NE;                       // appended self loops
    }
    s = min(max(s, 0), NN - 1);               // defensive: never fault
    d = min(max(d, 0), NN - 1);
    g_src[i] = s;
    g_dst[i] = d;
    atomicAdd(&g_deg[d], 1);
}

__global__ void scan1_k() {
    __shared__ int sh[1024];
    int i = blockIdx.x * 1024 + threadIdx.x;
    int v = (i < NN) ? g_deg[i] : 0;
    sh[threadIdx.x] = v;
    __syncthreads();
    for (int off = 1; off < 1024; off <<= 1) {
        int t = (threadIdx.x >= off) ? sh[threadIdx.x - off] : 0;
        __syncthreads();
        sh[threadIdx.x] += t;
        __syncthreads();
    }
    if (i < NN) g_tmp[i] = sh[threadIdx.x];
    if (threadIdx.x == 1023) g_bsums[blockIdx.x] = sh[1023];
}

// fused scan2+scan3
__global__ void scan3_k() {
    __shared__ int pref[NB + 1];
    if (threadIdx.x == 0) {
        int acc = 0;
        for (int b = 0; b < NB; b++) { pref[b] = acc; acc += g_bsums[b]; }
    }
    __syncthreads();
    int i = blockIdx.x * blockDim.x + threadIdx.x;
    if (i < NN) {
        int incl = g_tmp[i] + pref[i >> 10];
        g_rowptr[i + 1] = incl;
        g_fill[i] = incl - g_deg[i];           // exclusive prefix = fill cursor
    }
    if (i == 0) g_rowptr[0] = 0;
}

__global__ void scatter_k() {
    int i = blockIdx.x * blockDim.x + threadIdx.x;
    if (i >= ET) return;
    int pos = atomicAdd(&g_fill[g_dst[i]], 1);
    g_esrc[pos] = g_src[i];
}

// ---------------- fp16x3 dual tensor-core GEMM (m16n8k16) ----------------
// hi = RN16(x), lo = RN16(x - hi); hi*hi + hi*lo + lo*hi in fp32 accumulate.
__device__ __forceinline__ void mma16(float* c, const unsigned* a,
                                      unsigned b0, unsigned b1) {
    asm volatile(
        "mma.sync.aligned.m16n8k16.row.col.f32.f16.f16.f32 "
        "{%0,%1,%2,%3}, {%4,%5,%6,%7}, {%8,%9}, {%0,%1,%2,%3};"
        : "+f"(c[0]), "+f"(c[1]), "+f"(c[2]), "+f"(c[3])
        : "r"(a[0]), "r"(a[1]), "r"(a[2]), "r"(a[3]), "r"(b0), "r"(b1));
}

__device__ __forceinline__ void cp16(unsigned dst, const void* src, int srcBytes) {
    asm volatile("cp.async.ca.shared.global [%0], [%1], 16, %2;"
                 :: "r"(dst), "l"(src), "r"(srcBytes));
}

// hi/lo split of a float pair into two half2
__device__ __forceinline__ void split2(float x, float y, unsigned& hi, unsigned& lo) {
    __half2 h = __floats2half2_rn(x, y);
    __half2 l = __floats2half2_rn(x - __low2float(h), y - __high2float(h));
    hi = *reinterpret_cast<unsigned*>(&h);
    lo = *reinterpret_cast<unsigned*>(&l);
}

// A smem: [m][16], element k stored at k ^ (4*(m&3))   (conflict-free)
// B smem: [k][64], element n stored at n ^ ((4*k)&63)  (conflict-free)
__global__ __launch_bounds__(256, 2) void gemm_dual_k(
    const float* __restrict__ A,
    const float* __restrict__ Wl, const float* __restrict__ Wr,
    __half* __restrict__ Cl, float* __restrict__ Cr, int n, int oc)
{
    __shared__ float As[2][BM * 16];
    __shared__ float Bs[2][2][BK * 64];

    const int tid = threadIdx.x;
    const int lane = tid & 31, wid = tid >> 5;
    const int wm = wid >> 1, wn = wid & 1;       // 4 x 2 warp grid
    const int gid = lane >> 2, tig = lane & 3;
    const int row0 = blockIdx.x * BM;
    const int col0 = blockIdx.y * BN;

    float acc[2][2][4][4];                        // [side][i][j][reg]
#pragma unroll
    for (int sd = 0; sd < 2; sd++)
#pragma unroll
        for (int i = 0; i < 2; i++)
#pragma unroll
            for (int j = 0; j < 4; j++)
#pragma unroll
                for (int r = 0; r < 4; r++) acc[sd][i][j][r] = 0.f;

    const int ar = tid >> 1, kof = (tid & 1) * 8;          // A: 2 x 16B per thread
    const int br = tid >> 4, bc = (tid & 15) * 4;          // B: 1 x 16B per side
    const int aValid = (row0 + ar < n) ? 16 : 0;
    const int aswz = 4 * (ar & 3);
    const int bswz = (4 * br) & 63;

    auto load_stage = [&](int st, int kk) {
        const float* srcA = A + (size_t)(row0 + ar) * 128 + kk + kof;
        cp16((unsigned)__cvta_generic_to_shared(&As[st][ar * 16 + (kof ^ aswz)]),
             srcA, aValid);
        cp16((unsigned)__cvta_generic_to_shared(&As[st][ar * 16 + ((kof + 4) ^ aswz)]),
             srcA + 4, aValid);
        cp16((unsigned)__cvta_generic_to_shared(&Bs[st][0][br * 64 + (bc ^ bswz)]),
             Wl + (size_t)(kk + br) * oc + col0 + bc, 16);
        cp16((unsigned)__cvta_generic_to_shared(&Bs[st][1][br * 64 + (bc ^ bswz)]),
             Wr + (size_t)(kk + br) * oc + col0 + bc, 16);
    };

    load_stage(0, 0);
    asm volatile("cp.async.commit_group;");

    const int kp0 = 2 * tig;            // A k-pair base for a0/a1
#pragma unroll
    for (int it = 0; it < 8; it++) {
        const int buf = it & 1;
        if (it + 1 < 8) {
            load_stage(buf ^ 1, (it + 1) * BK);
            asm volatile("cp.async.commit_group;");
            asm volatile("cp.async.wait_group 1;");
        } else {
            asm volatile("cp.async.wait_group 0;");
        }
        __syncthreads();

        // A fragments (hi/lo), m16n8k16 layout
        unsigned ah[2][4], al[2][4];
#pragma unroll
        for (int i = 0; i < 2; i++) {
            const int m0 = wm * 32 + i * 16;
            const int r0 = m0 + gid, r1 = m0 + gid + 8;
            const int s0 = 4 * (r0 & 3), s1 = 4 * (r1 & 3);
            float2 f0 = *reinterpret_cast<const float2*>(&As[buf][r0 * 16 + (kp0 ^ s0)]);
            float2 f1 = *reinterpret_cast<const float2*>(&As[buf][r1 * 16 + (kp0 ^ s1)]);
            float2 f2 = *reinterpret_cast<const float2*>(&As[buf][r0 * 16 + ((kp0 + 8) ^ s0)]);
            float2 f3 = *reinterpret_cast<const float2*>(&As[buf][r1 * 16 + ((kp0 + 8) ^ s1)]);
            split2(f0.x, f0.y, ah[i][0], al[i][0]);
            split2(f1.x, f1.y, ah[i][1], al[i][1]);
            split2(f2.x, f2.y, ah[i][2], al[i][2]);
            split2(f3.x, f3.y, ah[i][3], al[i][3]);
        }

#pragma unroll
        for (int sd = 0; sd < 2; sd++) {
#pragma unroll
            for (int j = 0; j < 4; j++) {
                const int c = wn * 32 + j * 8 + gid;
                const int k00 = 2 * tig, k01 = k00 + 1;
                const int k10 = k00 + 8, k11 = k00 + 9;
                float b00 = Bs[buf][sd][k00 * 64 + (c ^ ((4 * k00) & 63))];
                float b01 = Bs[buf][sd][k01 * 64 + (c ^ ((4 * k01) & 63))];
                float b10 = Bs[buf][sd][k10 * 64 + (c ^ ((4 * k10) & 63))];
                float b11 = Bs[buf][sd][k11 * 64 + (c ^ ((4 * k11) & 63))];
                unsigned bh0, bl0, bh1, bl1;
                split2(b00, b01, bh0, bl0);
                split2(b10, b11, bh1, bl1);
#pragma unroll
                for (int i = 0; i < 2; i++) {
                    mma16(acc[sd][i][j], ah[i], bh0, bh1);
                    mma16(acc[sd][i][j], ah[i], bl0, bl1);
                    mma16(acc[sd][i][j], al[i], bh0, bh1);
                }
            }
        }
        __syncthreads();
    }

#pragma unroll
    for (int i = 0; i < 2; i++) {
        int rbase = row0 + wm * 32 + i * 16 + gid;
#pragma unroll
        for (int j = 0; j < 4; j++) {
            int c = col0 + wn * 32 + j * 8 + 2 * tig;
            if (rbase < n) {
                *reinterpret_cast<__half2*>(Cl + (size_t)rbase * oc + c) =
                    __floats2half2_rn(acc[0][i][j][0], acc[0][i][j][1]);
                *reinterpret_cast<float2*>(Cr + (size_t)rbase * oc + c) =
                    make_float2(acc[1][i][j][0], acc[1][i][j][1]);
            }
            if (rbase + 8 < n) {
                *reinterpret_cast<__half2*>(Cl + (size_t)(rbase + 8) * oc + c) =
                    __floats2half2_rn(acc[0][i][j][2], acc[0][i][j][3]);
                *reinterpret_cast<float2*>(Cr + (size_t)(rbase + 8) * oc + c) =
                    make_float2(acc[1][i][j][2], acc[1][i][j][3]);
            }
        }
    }
}

// ---------------- fused edge kernel: segment softmax + aggregate ----------
// One warp per destination node; self-loop score as fixed softmax offset.
// hl gathered in fp16 (halves L2 traffic vs fp32).
template <int H, int CH>
__global__ __launch_bounds__(256) void gat_edge(
    const __half* __restrict__ hl, const float* __restrict__ hr,
    const float* __restrict__ att, const float* __restrict__ bias,
    float* __restrict__ out)
{
    constexpr int V = CH / 32;
    const int w = (blockIdx.x * blockDim.x + threadIdx.x) >> 5;
    const int lane = threadIdx.x & 31;
    if (w >= NN) return;

    float attv[V], hrv[V], acc[V];
#pragma unroll
    for (int v = 0; v < V; v++) attv[v] = att[lane * V + v];

    if (V == 4) {
        float4 t = __ldg(reinterpret_cast<const float4*>(hr) + w * 32 + lane);
        hrv[0] = t.x; hrv[1] = t.y; hrv[2] = t.z; hrv[3] = t.w;
    } else {
        float2 t = __ldg(reinterpret_cast<const float2*>(hr) + w * 32 + lane);
        hrv[0] = t.x; hrv[1] = t.y;
    }
#pragma unroll
    for (int v = 0; v < V; v++) acc[v] = 0.f;

    auto gather = [&](int s, float* hv) {
        if (V == 4) {
            uint2 t = __ldg(reinterpret_cast<const uint2*>(hl) + s * 32 + lane);
            float2 f01 = __half22float2(*reinterpret_cast<__half2*>(&t.x));
            float2 f23 = __half22float2(*reinterpret_cast<__half2*>(&t.y));
            hv[0] = f01.x; hv[1] = f01.y; hv[2] = f23.x; hv[3] = f23.y;
        } else {
            unsigned t = __ldg(reinterpret_cast<const unsigned*>(hl) + s * 32 + lane);
            float2 f = __half22float2(*reinterpret_cast<__half2*>(&t));
            hv[0] = f.x; hv[1] = f.y;
        }
    };

    auto score = [&](const float* hv) {
        float p = 0.f;
#pragma unroll
        for (int v = 0; v < V; v++) {
            float t = hv[v] + hrv[v];
            t = (t > 0.f) ? t : 0.2f * t;          // LeakyReLU(0.2)
            p = fmaf(t, attv[v], p);
        }
#pragma unroll
        for (int off = (32 / H) >> 1; off > 0; off >>= 1)
            p += __shfl_xor_sync(0xffffffffu, p, off);
        return p;
    };

    float p_self;
    {
        float hs[V];
        gather(w, hs);
        p_self = score(hs);
    }

    float lsum = 0.f;
    const int e0 = g_rowptr[w], e1 = g_rowptr[w + 1];

    auto update = [&](const float* hv) {
        float p = score(hv);
        float ww = __expf(p - p_self);
        lsum += ww;
#pragma unroll
        for (int v = 0; v < V; v++) acc[v] = fmaf(ww, hv[v], acc[v]);
    };

    int e = e0;
    for (; e + 4 <= e1; e += 4) {
        int s0 = __ldg(&g_esrc[e]);
        int s1 = __ldg(&g_esrc[e + 1]);
        int s2 = __ldg(&g_esrc[e + 2]);
        int s3 = __ldg(&g_esrc[e + 3]);
        float hv0[V], hv1[V], hv2[V], hv3[V];
        gather(s0, hv0); gather(s1, hv1); gather(s2, hv2); gather(s3, hv3);
        update(hv0); update(hv1); update(hv2); update(hv3);
    }
    for (; e < e1; e++) {
        int s = __ldg(&g_esrc[e]);
        float hv[V];
        gather(s, hv);
        update(hv);
    }

    float inv = 1.f / (lsum + 1e-16f);
    if (V == 4) {
        float4 o;
        o.x = fmaxf(fmaf(acc[0], inv, bias[lane * 4 + 0]), 0.f);
        o.y = fmaxf(fmaf(acc[1], inv, bias[lane * 4 + 1]), 0.f);
        o.z = fmaxf(fmaf(acc[2], inv, bias[lane * 4 + 2]), 0.f);
        o.w = fmaxf(fmaf(acc[3], inv, bias[lane * 4 + 3]), 0.f);
        reinterpret_cast<float4*>(out)[w * 32 + lane] = o;
    } else {
        float2 o;
        o.x = fmaxf(fmaf(acc[0], inv, bias[lane * 2 + 0]), 0.f);
        o.y = fmaxf(fmaf(acc[1], inv, bias[lane * 2 + 1]), 0.f);
        reinterpret_cast<float2*>(out)[w * 32 + lane] = o;
    }
}

// ---------------- launch ----------------
extern "C" void kernel_launch(void* const* d_in, const int* in_sizes, int n_in,
                              void* d_out, int out_size)
{
    const float* x   = (const float*)d_in[0];
    const void*  ei  = d_in[1];
    const float *W0l = (const float*)d_in[2],  *W0r = (const float*)d_in[3];
    const float *a0  = (const float*)d_in[4],  *b0  = (const float*)d_in[5];
    const float *W1l = (const float*)d_in[6],  *W1r = (const float*)d_in[7];
    const float *a1  = (const float*)d_in[8],  *b1  = (const float*)d_in[9];
    const float *W2l = (const float*)d_in[10], *W2r = (const float*)d_in[11];
    const float *a2  = (const float*)d_in[12], *b2  = (const float*)d_in[13];
    float* out = (float*)d_out;

    void *p_hlh, *p_hr, *p_h;
    cudaGetSymbolAddress(&p_hlh, g_hlh);
    cudaGetSymbolAddress(&p_hr, g_hr);
    cudaGetSymbolAddress(&p_h, g_h);
    __half* hl = (__half*)p_hlh;
    float*  hr = (float*)p_hr;
    float*  h  = (float*)p_h;

    const int eb = (ET + 255) / 256;
    const dim3 gg((NN + BM - 1) / BM, 2);
    const dim3 gg2((NN + BM - 1) / BM, 1);
    const int egrid = (NN * 32 + 255) / 256;

    zero_detect_k<<<(NN + 1023) / 1024, 1024>>>((const int*)ei);     // 1
    convert_count_k<<<eb, 256>>>(ei);                                // 2
    scan1_k<<<NB, 1024>>>();                                         // 3
    gemm_dual_k<<<gg, 256>>>(x, W0l, W0r, hl, hr, NN, 128);          // 4 <- profiled
    scan3_k<<<(NN + 255) / 256, 256>>>();                            // 5
    scatter_k<<<eb, 256>>>();                                        // 6
    gat_edge<4, 128><<<egrid, 256>>>(hl, hr, a0, b0, h);             // 7
    gemm_dual_k<<<gg, 256>>>(h, W1l, W1r, hl, hr, NN, 128);          // 8
    gat_edge<4, 128><<<egrid, 256>>>(hl, hr, a1, b1, h);             // 9
    gemm_dual_k<<<gg2, 256>>>(h, W2l, W2r, hl, hr, NN, 64);          // 10
    gat_edge<1, 64><<<egrid, 256>>>(hl, hr, a2, b2, out);            // 11
}